// round 12
// baseline (speedup 1.0000x reference)
#include <cuda_runtime.h>
#include <math.h>

#define BATCH 64
#define SEQ   197
#define EMB   640
#define NH    10
#define HDIM_ 64
#define FF    2560
#define MROWS (BATCH*SEQ)          /* 12608 */
#define ATTS  208                  /* padded attn row stride */
#define BHN   (BATCH*NH)           /* 640 */
#define QKVS  1920                 /* fused qkv row stride */

/* ------------------------- scratch (device globals) ------------------------ */
__device__ float g_h  [MROWS*EMB];
__device__ float g_qkv[(size_t)MROWS*QKVS];     /* [q|k|v] per row */
__device__ float g_o  [MROWS*EMB];
__device__ float g_x1 [MROWS*EMB];
__device__ float g_ffn[(size_t)MROWS*FF];
__device__ float g_attn[(size_t)BHN*SEQ*ATTS];
__device__ float g_qtab[(size_t)MROWS*600];
__device__ float g_stab[(size_t)BHN*SEQ*64];
__device__ float g_rcat[64*64];                 /* TRANSPOSED: [d][t] */
/* pre-rounded (tf32) weights */
__device__ float g_wqkv[(size_t)QKVS*EMB];      /* [Wq;Wk;Wv] */
__device__ float g_wp[EMB*EMB];
__device__ float g_w1[(size_t)FF*EMB];
__device__ float g_w2[(size_t)FF*EMB];

/* ------------------------------ tf32 helpers ------------------------------- */
__device__ __forceinline__ unsigned f2tf(float f)
{
    unsigned r;
    asm("cvt.rna.tf32.f32 %0, %1;" : "=r"(r) : "f"(f));
    return r;
}
__device__ __forceinline__ float tf32r(float f) { return __uint_as_float(f2tf(f)); }

__device__ __forceinline__ void mma_tf32(float* c, const unsigned* a, const unsigned* b)
{
    asm volatile(
        "mma.sync.aligned.m16n8k8.row.col.f32.tf32.tf32.f32 "
        "{%0,%1,%2,%3},{%4,%5,%6,%7},{%8,%9},{%0,%1,%2,%3};"
        : "+f"(c[0]), "+f"(c[1]), "+f"(c[2]), "+f"(c[3])
        : "r"(a[0]), "r"(a[1]), "r"(a[2]), "r"(a[3]), "r"(b[0]), "r"(b[1]));
}

#define CP16(dst, src, ok) \
    asm volatile("cp.async.cg.shared.global [%0], [%1], 16, %2;" \
        :: "r"(dst), "l"(src), "r"((ok) ? 16 : 0))

/* ------------------------------ rpe indexing ------------------------------- */
__device__ __forceinline__ void rpe_idx(int n, int m, int &iv, int &ih)
{
    if (n == 0 || m == 0) { iv = 0; ih = 0; return; }
    int r = n - 1, c = m - 1;
    int dv = c / 14 - r / 14;
    int dh = c % 14 - r % 14;
    dv = dv < -14 ? -14 : (dv > 14 ? 14 : dv);
    dh = dh < -14 ? -14 : (dh > 14 ? 14 : dh);
    iv = dv + 15; ih = dh + 15;
}

/* -------------------- layer norm (output tf32-rounded) --------------------- */
__global__ void __launch_bounds__(256) ln_kernel(const float* __restrict__ x,
        const float* __restrict__ gam, const float* __restrict__ bet,
        float* __restrict__ out)
{
    int w    = (blockIdx.x * blockDim.x + threadIdx.x) >> 5;
    int lane = threadIdx.x & 31;
    if (w >= MROWS) return;
    const float* r = x + (size_t)w * EMB;
    float v[20]; float s = 0.f, s2 = 0.f;
#pragma unroll
    for (int i = 0; i < 20; i++) {
        float t = r[lane + 32 * i]; v[i] = t; s += t; s2 += t * t;
    }
#pragma unroll
    for (int o = 16; o; o >>= 1) {
        s  += __shfl_xor_sync(0xffffffffu, s,  o);
        s2 += __shfl_xor_sync(0xffffffffu, s2, o);
    }
    float mu  = s * (1.f / EMB);
    float var = s2 * (1.f / EMB) - mu * mu;
    float inv = rsqrtf(var + 1e-5f);
    float* o_ = out + (size_t)w * EMB;
#pragma unroll
    for (int i = 0; i < 20; i++) {
        int c = lane + 32 * i;
        o_[c] = tf32r((v[i] - mu) * inv * gam[c] + bet[c]);
    }
}

/* ------------------------ weight pre-round (once) -------------------------- */
__global__ void __launch_bounds__(256) round_copy(const float* __restrict__ src,
                                                  float* __restrict__ dst, int n)
{
    int i = blockIdx.x * 256 + threadIdx.x;
    if (i < n) dst[i] = __uint_as_float(f2tf(src[i]));
}

__global__ void __launch_bounds__(256) round_qkv(const float* __restrict__ wq,
        const float* __restrict__ wk, const float* __restrict__ wv)
{
    const int EE = EMB * EMB;
    int i = blockIdx.x * 256 + threadIdx.x;
    if (i >= 3 * EE) return;
    const float* src = (i < EE) ? wq : (i < 2 * EE ? wk : wv);
    int j = i - (i < EE ? 0 : (i < 2 * EE ? EE : 2 * EE));
    g_wqkv[i] = __uint_as_float(f2tf(src[j]));
}

/* ---------------- C = A @ W^T (+bias,res,gelu), TF32 tensor cores ---------- */
template<bool GELU, bool ROUND>
__global__ void __launch_bounds__(256, 2) gemm_tc(const float* __restrict__ A,
        const float* __restrict__ W, const float* __restrict__ bias,
        const float* __restrict__ res, float* __restrict__ C,
        int K, int Nc, int Mtot)
{
    __shared__ unsigned As[3][128][20];
    __shared__ unsigned Bs[3][128][20];

    int tid  = threadIdx.x;
    int warp = tid >> 5, lane = tid & 31;
    int m0 = blockIdx.y * 128, n0 = blockIdx.x * 128;
    int wm = warp & 1, wn = warp >> 1;
    int g  = lane >> 2, t = lane & 3;

    int lr = tid >> 2, lc = tid & 3;
    const float* Ap0 = A + (size_t)(m0 + lr)      * K + lc * 4;
    const float* Ap1 = A + (size_t)(m0 + lr + 64) * K + lc * 4;
    const float* Wp0 = W + (size_t)(n0 + lr)      * K + lc * 4;
    const float* Wp1 = W + (size_t)(n0 + lr + 64) * K + lc * 4;
    bool am0 = (m0 + lr) < Mtot, am1 = (m0 + lr + 64) < Mtot;

    unsigned sA = (unsigned)__cvta_generic_to_shared(As);
    unsigned sB = (unsigned)__cvta_generic_to_shared(Bs);
    unsigned off0 = (lr * 20 + lc * 4) * 4;
    unsigned off1 = ((lr + 64) * 20 + lc * 4) * 4;
    const unsigned BUFB = 128 * 20 * 4;

    float acc[4][4][4];
#pragma unroll
    for (int mi = 0; mi < 4; mi++)
#pragma unroll
        for (int ni = 0; ni < 4; ni++)
#pragma unroll
            for (int e = 0; e < 4; e++) acc[mi][ni][e] = 0.f;

    int nkt = K >> 4;

    auto issue = [&](int kt, int buf) {
        unsigned ba = sA + buf * BUFB, bb = sB + buf * BUFB;
        CP16(ba + off0, Ap0 + kt * 16, am0);
        CP16(ba + off1, Ap1 + kt * 16, am1);
        CP16(bb + off0, Wp0 + kt * 16, 1);
        CP16(bb + off1, Wp1 + kt * 16, 1);
        asm volatile("cp.async.commit_group;");
    };

    issue(0, 0);
    if (nkt > 1) issue(1, 1);

    for (int kt = 0; kt < nkt; kt++) {
        if (kt + 1 < nkt) asm volatile("cp.async.wait_group 1;");
        else              asm volatile("cp.async.wait_group 0;");
        __syncthreads();
        int buf = kt % 3;
#pragma unroll
        for (int ks = 0; ks < 2; ks++) {
            unsigned af[4][4], bf[4][2];
            int kc = ks * 8 + t;
#pragma unroll
            for (int mi = 0; mi < 4; mi++) {
                int r = wm * 64 + mi * 16 + g;
                af[mi][0] = As[buf][r][kc];
                af[mi][1] = As[buf][r + 8][kc];
                af[mi][2] = As[buf][r][kc + 4];
                af[mi][3] = As[buf][r + 8][kc + 4];
            }
#pragma unroll
            for (int ni = 0; ni < 4; ni++) {
                int r = wn * 32 + ni * 8 + g;
                bf[ni][0] = Bs[buf][r][kc];
                bf[ni][1] = Bs[buf][r][kc + 4];
            }
#pragma unroll
            for (int mi = 0; mi < 4; mi++)
#pragma unroll
                for (int ni = 0; ni < 4; ni++)
                    mma_tf32(acc[mi][ni], af[mi], bf[ni]);
        }
        if (kt + 2 < nkt) issue(kt + 2, (kt + 2) % 3);
    }

#pragma unroll
    for (int mi = 0; mi < 4; mi++) {
#pragma unroll
        for (int half = 0; half < 2; half++) {
            int r = m0 + wm * 64 + mi * 16 + g + half * 8;
            if (r >= Mtot) continue;
#pragma unroll
            for (int ni = 0; ni < 4; ni++) {
                int c = n0 + wn * 32 + ni * 8 + 2 * t;
                float vx = acc[mi][ni][half * 2 + 0];
                float vy = acc[mi][ni][half * 2 + 1];
                if (bias) { vx += bias[c]; vy += bias[c + 1]; }
                if (res) {
                    const float* rp = res + (size_t)r * Nc + c;
                    vx += rp[0]; vy += rp[1];
                }
                if (GELU) { vx *= normcdff(vx); vy *= normcdff(vy); }
                if (ROUND) { vx = tf32r(vx); vy = tf32r(vy); }
                float2 out2; out2.x = vx; out2.y = vy;
                *(float2*)(C + (size_t)r * Nc + c) = out2;
            }
        }
    }
}

/* ---------------- qtab[b,n][h][t] = q[b,n,h,:] . rpk_{v|h}[t,:] ------------ */
__global__ void __launch_bounds__(256) qtab_kernel(const float* __restrict__ rpkv,
                                                   const float* __restrict__ rpkh)
{
    __shared__ float qs[EMB];
    __shared__ float tabs[60][65];
    int row = blockIdx.x;
    int tid = threadIdx.x;
    const float* qrow = g_qkv + (size_t)row * QKVS;
    for (int i = tid; i < EMB; i += 256) qs[i] = qrow[i];
    for (int i = tid; i < 1920; i += 256) tabs[i >> 6][i & 63]        = rpkv[i];
    for (int i = tid; i < 1920; i += 256) tabs[30 + (i >> 6)][i & 63] = rpkh[i];
    __syncthreads();
    for (int idx = tid; idx < 600; idx += 256) {
        int h = idx / 60, t = idx - h * 60;
        float s = 0.f;
#pragma unroll
        for (int d = 0; d < 64; d++) s = fmaf(qs[h * 64 + d], tabs[t][d], s);
        g_qtab[(size_t)row * 600 + idx] = s;
    }
}

/* ------------------ rcat TRANSPOSED: g_rcat[d][t] = table[t][d] ------------ */
__global__ void build_rcat(const float* __restrict__ rv, const float* __restrict__ rh)
{
    int i = blockIdx.x * 256 + threadIdx.x;
    if (i >= 64 * 64) return;
    int d = i >> 6, t = i & 63;
    float v = 0.f;
    if (t < 30) v = rv[t * 64 + d];
    else if (t < 60) v = rh[(t - 30) * 64 + d];
    g_rcat[i] = v;
}

/* ------- scores via tf32 MMA: attn = 0.125*(q.k + qtab gathers) ------------ */
__global__ void __launch_bounds__(128) scores_tc()
{
    __shared__ unsigned Qs[64][68];   /* stride 68: 4g+t conflict-free */
    __shared__ unsigned Ks[64][68];
    int bh = blockIdx.z, b = bh / NH, h = bh - b * NH;
    int m0 = blockIdx.x * 64, n0 = blockIdx.y * 64;
    int tid = threadIdx.x, warp = tid >> 5, lane = tid & 31;
    int wm = warp & 1, wn = warp >> 1;
    int g = lane >> 2, t = lane & 3;

    const float* Qb = g_qkv + (size_t)b * SEQ * QKVS + h * HDIM_;
    const float* Kb = Qb + EMB;

    int srow = tid >> 1, shalf = tid & 1;
    bool qok = (n0 + srow) < SEQ, kok = (m0 + srow) < SEQ;
    const float* Qg = Qb + (size_t)(n0 + srow) * QKVS;
    const float* Kg = Kb + (size_t)(m0 + srow) * QKVS;
    float4 z4 = make_float4(0.f, 0.f, 0.f, 0.f);
#pragma unroll
    for (int j = 0; j < 8; j++) {
        int c4 = shalf * 8 + j;
        float4 qv = qok ? *(const float4*)(Qg + c4 * 4) : z4;
        float4 kv = kok ? *(const float4*)(Kg + c4 * 4) : z4;
        uint4 u;
        u.x = f2tf(qv.x); u.y = f2tf(qv.y); u.z = f2tf(qv.z); u.w = f2tf(qv.w);
        *(uint4*)&Qs[srow][c4 * 4] = u;
        u.x = f2tf(kv.x); u.y = f2tf(kv.y); u.z = f2tf(kv.z); u.w = f2tf(kv.w);
        *(uint4*)&Ks[srow][c4 * 4] = u;
    }
    __syncthreads();

    float acc[2][4][4];
#pragma unroll
    for (int mi = 0; mi < 2; mi++)
#pragma unroll
        for (int ni = 0; ni < 4; ni++)
#pragma unroll
            for (int e = 0; e < 4; e++) acc[mi][ni][e] = 0.f;

#pragma unroll
    for (int ks = 0; ks < 8; ks++) {
        int kc = ks * 8 + t;
        unsigned af[2][4], bf[4][2];
#pragma unroll
        for (int mi = 0; mi < 2; mi++) {
            int r = wm * 32 + mi * 16 + g;
            af[mi][0] = Qs[r][kc];     af[mi][1] = Qs[r + 8][kc];
            af[mi][2] = Qs[r][kc + 4]; af[mi][3] = Qs[r + 8][kc + 4];
        }
#pragma unroll
        for (int ni = 0; ni < 4; ni++) {
            int r = wn * 32 + ni * 8 + g;
            bf[ni][0] = Ks[r][kc]; bf[ni][1] = Ks[r][kc + 4];
        }
#pragma unroll
        for (int mi = 0; mi < 2; mi++)
#pragma unroll
            for (int ni = 0; ni < 4; ni++)
                mma_tf32(acc[mi][ni], af[mi], bf[ni]);
    }

#pragma unroll
    for (int mi = 0; mi < 2; mi++) {
#pragma unroll
        for (int half = 0; half < 2; half++) {
            int n = n0 + wm * 32 + mi * 16 + g + half * 8;
            if (n >= SEQ) continue;
            const float* qt = g_qtab + (size_t)(b * SEQ + n) * 600 + h * 60;
            float* arow = g_attn + ((size_t)bh * SEQ + n) * ATTS;
#pragma unroll
            for (int ni = 0; ni < 4; ni++) {
#pragma unroll
                for (int e = 0; e < 2; e++) {
                    int m = m0 + wn * 32 + ni * 8 + 2 * t + e;
                    if (m >= ATTS) continue;
                    float val = 0.f;
                    if (m < SEQ) {
                        int iv, ih; rpe_idx(n, m, iv, ih);
                        val = 0.125f * (acc[mi][ni][half * 2 + e] + qt[iv] + qt[30 + ih]);
                    }
                    arow[m] = val;
                }
            }
        }
    }
}

/* ------------- softmax over m + bin probabilities by (iv, ih) -------------- */
__global__ void __launch_bounds__(256) softmax_kernel()
{
    __shared__ float bins[8][64];
    int wl = threadIdx.x >> 5, lane = threadIdx.x & 31;
    int w = blockIdx.x * 8 + wl;
    if (w >= BHN * SEQ) return;
    int n = w % SEQ;
    float* row = g_attn + (size_t)w * ATTS;

    float e[7]; float mx = -1e30f;
#pragma unroll
    for (int i = 0; i < 7; i++) {
        int m = lane + 32 * i;
        float v = (m < SEQ) ? row[m] : -1e30f;
        e[i] = v; mx = fmaxf(mx, v);
    }
#pragma unroll
    for (int o = 16; o; o >>= 1) mx = fmaxf(mx, __shfl_xor_sync(0xffffffffu, mx, o));
    float s = 0.f;
#pragma unroll
    for (int i = 0; i < 7; i++) {
        int m = lane + 32 * i;
        float ev = (m < SEQ) ? __expf(e[i] - mx) : 0.f;
        e[i] = ev; s += ev;
    }
#pragma unroll
    for (int o = 16; o; o >>= 1) s += __shfl_xor_sync(0xffffffffu, s, o);
    float inv = 1.f / s;

    bins[wl][lane] = 0.f; bins[wl][lane + 32] = 0.f;
    __syncwarp();
#pragma unroll
    for (int i = 0; i < 7; i++) {
        int m = lane + 32 * i;
        if (m < SEQ) {
            float p = e[i] * inv;
            row[m] = p;
            int iv, ih; rpe_idx(n, m, iv, ih);
            atomicAdd(&bins[wl][iv], p);
            atomicAdd(&bins[wl][32 + ih], p);
        }
    }
    __syncwarp();
    float* st = g_stab + (size_t)w * 64;
    for (int t = lane; t < 64; t += 32) {
        float v = (t < 30) ? bins[wl][t] : (t < 60 ? bins[wl][32 + (t - 30)] : 0.f);
        st[t] = v;
    }
}

/* -------- o = P @ V + stab @ rcat via tf32 MMA (5 K-phases of 64) ---------- */
__global__ void __launch_bounds__(128) attnv_tc()
{
    __shared__ unsigned Ps[64][68];
    __shared__ unsigned Vs[64][68];   /* transposed: [d][m_local] */
    int bh = blockIdx.y, b = bh / NH, h = bh - b * NH;
    int n0 = blockIdx.x * 64;
    int tid = threadIdx.x, warp = tid >> 5, lane = tid & 31;
    int wm = warp & 1, wn = warp >> 1;
    int g = lane >> 2, t = lane & 3;

    const float* Pb = g_attn + (size_t)bh * SEQ * ATTS;
    const float* Vb = g_qkv  + (size_t)b * SEQ * QKVS + h * HDIM_ + 2 * EMB;
    const float* Sb = g_stab + (size_t)bh * SEQ * 64;

    int srow = tid >> 1, shalf = tid & 1;
    bool nok = (n0 + srow) < SEQ;
    float4 z4 = make_float4(0.f, 0.f, 0.f, 0.f);

    float acc[2][4][4];
#pragma unroll
    for (int mi = 0; mi < 2; mi++)
#pragma unroll
        for (int ni = 0; ni < 4; ni++)
#pragma unroll
            for (int e = 0; e < 4; e++) acc[mi][ni][e] = 0.f;

    for (int kt = 0; kt < 5; kt++) {
        __syncthreads();
        if (kt < 4) {
            const float* Pg = Pb + (size_t)(n0 + srow) * ATTS + kt * 64;
#pragma unroll
            for (int j = 0; j < 8; j++) {
                int c4 = shalf * 8 + j;
                int mabs = kt * 64 + c4 * 4;
                float4 pv = (nok && mabs + 3 < ATTS) ? *(const float4*)(Pg + c4 * 4) : z4;
                uint4 u;
                u.x = f2tf(pv.x); u.y = f2tf(pv.y); u.z = f2tf(pv.z); u.w = f2tf(pv.w);
                *(uint4*)&Ps[srow][c4 * 4] = u;
            }
            int m = kt * 64 + srow;
            bool vok = m < SEQ;
            const float* Vg = Vb + (size_t)m * QKVS;
#pragma unroll
            for (int j = 0; j < 8; j++) {
                int d4 = shalf * 8 + j;
                float4 vv = vok ? *(const float4*)(Vg + d4 * 4) : z4;
                Vs[d4 * 4 + 0][srow] = f2tf(vv.x);
                Vs[d4 * 4 + 1][srow] = f2tf(vv.y);
                Vs[d4 * 4 + 2][srow] = f2tf(vv.z);
                Vs[d4 * 4 + 3][srow] = f2tf(vv.w);
            }
        } else {
            const float* Sg = Sb + (size_t)(n0 + srow) * 64;
#pragma unroll
            for (int j = 0; j < 8; j++) {
                int c4 = shalf * 8 + j;
                float4 sv = nok ? *(const float4*)(Sg + c4 * 4) : z4;
                uint4 u;
                u.x = f2tf(sv.x); u.y = f2tf(sv.y); u.z = f2tf(sv.z); u.w = f2tf(sv.w);
                *(uint4*)&Ps[srow][c4 * 4] = u;
                float4 rv = *(const float4*)(g_rcat + srow * 64 + c4 * 4);
                u.x = f2tf(rv.x); u.y = f2tf(rv.y); u.z = f2tf(rv.z); u.w = f2tf(rv.w);
                *(uint4*)&Vs[srow][c4 * 4] = u;
            }
        }
        __syncthreads();
#pragma unroll
        for (int ks = 0; ks < 8; ks++) {
            int kc = ks * 8 + t;
            unsigned af[2][4], bf[4][2];
#pragma unroll
            for (int mi = 0; mi < 2; mi++) {
                int r = wm * 32 + mi * 16 + g;
                af[mi][0] = Ps[r][kc];     af[mi][1] = Ps[r + 8][kc];
                af[mi][2] = Ps[r][kc + 4]; af[mi][3] = Ps[r + 8][kc + 4];
            }
#pragma unroll
            for (int ni = 0; ni < 4; ni++) {
                int r = wn * 32 + ni * 8 + g;
                bf[ni][0] = Vs[r][kc]; bf[ni][1] = Vs[r][kc + 4];
            }
#pragma unroll
            for (int mi = 0; mi < 2; mi++)
#pragma unroll
                for (int ni = 0; ni < 4; ni++)
                    mma_tf32(acc[mi][ni], af[mi], bf[ni]);
        }
    }

#pragma unroll
    for (int mi = 0; mi < 2; mi++) {
#pragma unroll
        for (int half = 0; half < 2; half++) {
            int n = n0 + wm * 32 + mi * 16 + g + half * 8;
            if (n >= SEQ) continue;
            float* orow = g_o + (size_t)(b * SEQ + n) * EMB + h * HDIM_;
#pragma unroll
            for (int ni = 0; ni < 4; ni++) {
                int d = wn * 32 + ni * 8 + 2 * t;
                float2 o2;
                o2.x = tf32r(acc[mi][ni][half * 2 + 0]);
                o2.y = tf32r(acc[mi][ni][half * 2 + 1]);
                *(float2*)(orow + d) = o2;
            }
        }
    }
}

/* --------------------------------- launch ---------------------------------- */
extern "C" void kernel_launch(void* const* d_in, const int* in_sizes, int n_in,
                              void* d_out, int out_size)
{
    const float* x     = (const float*)d_in[0];
    const float* ln1_g = (const float*)d_in[1];
    const float* ln1_b = (const float*)d_in[2];
    const float* Wq    = (const float*)d_in[3];
    const float* Wk    = (const float*)d_in[4];
    const float* Wv    = (const float*)d_in[5];
    const float* Wp    = (const float*)d_in[6];
    const float* bp    = (const float*)d_in[7];
    const float* rpk_v = (const float*)d_in[8];
    const float* rpk_h = (const float*)d_in[9];
    const float* rpv_v = (const float*)d_in[10];
    const float* rpv_h = (const float*)d_in[11];
    const float* ln2_g = (const float*)d_in[12];
    const float* ln2_b = (const float*)d_in[13];
    const float* W1    = (const float*)d_in[14];
    const float* b1    = (const float*)d_in[15];
    const float* W2    = (const float*)d_in[16];
    const float* b2    = (const float*)d_in[17];

    float *ph, *pqkv, *po, *px1, *pffn;
    float *pwqkv, *pwp, *pw1, *pw2;
    cudaGetSymbolAddress((void**)&ph,    g_h);
    cudaGetSymbolAddress((void**)&pqkv,  g_qkv);
    cudaGetSymbolAddress((void**)&po,    g_o);
    cudaGetSymbolAddress((void**)&px1,   g_x1);
    cudaGetSymbolAddress((void**)&pffn,  g_ffn);
    cudaGetSymbolAddress((void**)&pwqkv, g_wqkv);
    cudaGetSymbolAddress((void**)&pwp,   g_wp);
    cudaGetSymbolAddress((void**)&pw1,   g_w1);
    cudaGetSymbolAddress((void**)&pw2,   g_w2);

    const int MB = (MROWS + 127) / 128;   /* 99 */
    const int WEE = EMB * EMB, WFE = FF * EMB;

    /* weight pre-rounding (tf32) */
    round_qkv<<<(3 * WEE + 255) / 256, 256>>>(Wq, Wk, Wv);
    round_copy<<<(WEE + 255) / 256, 256>>>(Wp, pwp, WEE);
    round_copy<<<(WFE + 255) / 256, 256>>>(W1, pw1, WFE);
    round_copy<<<(WFE + 255) / 256, 256>>>(W2, pw2, WFE);

    /* LN1 (tf32-rounded output) */
    ln_kernel<<<MROWS / 8, 256>>>(x, ln1_g, ln1_b, ph);
    /* fused QKV projection */
    gemm_tc<false,false><<<dim3(QKVS / 128, MB), 256>>>(ph, pwqkv, nullptr, nullptr, pqkv, EMB, QKVS, MROWS);
    /* RPE precomputes */
    build_rcat<<<16, 256>>>(rpv_v, rpv_h);
    qtab_kernel<<<MROWS, 256>>>(rpk_v, rpk_h);
    /* attention (tensor cores) */
    scores_tc<<<dim3(4, 4, BHN), 128>>>();
    softmax_kernel<<<(BHN * SEQ + 7) / 8, 256>>>();
    attnv_tc<<<dim3(4, BHN), 128>>>();
    /* output projection + residual */
    gemm_tc<false,false><<<dim3(EMB / 128, MB), 256>>>(po, pwp, bp, x, px1, EMB, EMB, MROWS);
    /* FFN block */
    ln_kernel<<<MROWS / 8, 256>>>(px1, ln2_g, ln2_b, ph);
    gemm_tc<true ,true ><<<dim3(FF / 128, MB), 256>>>(ph, pw1, b1, nullptr, pffn, EMB, FF, MROWS);
    gemm_tc<false,false><<<dim3(EMB / 128, MB), 256>>>(pffn, pw2, b2, px1, (float*)d_out, FF, EMB, MROWS);
}

// round 13
// speedup vs baseline: 1.0084x; 1.0084x over previous
#include <cuda_runtime.h>
#include <math.h>

#define BATCH 64
#define SEQ   197
#define EMB   640
#define NH    10
#define HDIM_ 64
#define FF    2560
#define MROWS (BATCH*SEQ)          /* 12608 */
#define ATTS  208                  /* padded attn row stride */
#define BHN   (BATCH*NH)           /* 640 */
#define QKVS  1920                 /* fused qkv row stride */

/* ------------------------- scratch (device globals) ------------------------ */
__device__ float g_h  [MROWS*EMB];
__device__ float g_qkv[(size_t)MROWS*QKVS];     /* [q|k|v] per row */
__device__ float g_o  [MROWS*EMB];
__device__ float g_x1 [MROWS*EMB];
__device__ float g_ffn[(size_t)MROWS*FF];
__device__ float g_attn[(size_t)BHN*SEQ*ATTS];
__device__ float g_qtab[(size_t)MROWS*600];
__device__ float g_stab[(size_t)BHN*SEQ*64];
__device__ float g_rcat[64*64];                 /* TRANSPOSED: [d][t] */
/* pre-rounded (tf32) weights */
__device__ float g_wqkv[(size_t)QKVS*EMB];      /* [Wq;Wk;Wv] */
__device__ float g_wp[EMB*EMB];
__device__ float g_w1[(size_t)FF*EMB];
__device__ float g_w2[(size_t)FF*EMB];

/* ------------------------------ tf32 helpers ------------------------------- */
__device__ __forceinline__ unsigned f2tf(float f)
{
    unsigned r;
    asm("cvt.rna.tf32.f32 %0, %1;" : "=r"(r) : "f"(f));
    return r;
}
__device__ __forceinline__ float tf32r(float f) { return __uint_as_float(f2tf(f)); }

__device__ __forceinline__ void mma_tf32(float* c, const unsigned* a, const unsigned* b)
{
    asm volatile(
        "mma.sync.aligned.m16n8k8.row.col.f32.tf32.tf32.f32 "
        "{%0,%1,%2,%3},{%4,%5,%6,%7},{%8,%9},{%0,%1,%2,%3};"
        : "+f"(c[0]), "+f"(c[1]), "+f"(c[2]), "+f"(c[3])
        : "r"(a[0]), "r"(a[1]), "r"(a[2]), "r"(a[3]), "r"(b[0]), "r"(b[1]));
}

#define CP16(dst, src, ok) \
    asm volatile("cp.async.cg.shared.global [%0], [%1], 16, %2;" \
        :: "r"(dst), "l"(src), "r"((ok) ? 16 : 0))

/* ------------------------------ rpe indexing ------------------------------- */
__device__ __forceinline__ void rpe_idx(int n, int m, int &iv, int &ih)
{
    if (n == 0 || m == 0) { iv = 0; ih = 0; return; }
    int r = n - 1, c = m - 1;
    int dv = c / 14 - r / 14;
    int dh = c % 14 - r % 14;
    dv = dv < -14 ? -14 : (dv > 14 ? 14 : dv);
    dh = dh < -14 ? -14 : (dh > 14 ? 14 : dh);
    iv = dv + 15; ih = dh + 15;
}

/* -------------------- layer norm (output tf32-rounded) --------------------- */
__global__ void __launch_bounds__(256) ln_kernel(const float* __restrict__ x,
        const float* __restrict__ gam, const float* __restrict__ bet,
        float* __restrict__ out)
{
    int w    = (blockIdx.x * blockDim.x + threadIdx.x) >> 5;
    int lane = threadIdx.x & 31;
    if (w >= MROWS) return;
    const float* r = x + (size_t)w * EMB;
    float v[20]; float s = 0.f, s2 = 0.f;
#pragma unroll
    for (int i = 0; i < 20; i++) {
        float t = r[lane + 32 * i]; v[i] = t; s += t; s2 += t * t;
    }
#pragma unroll
    for (int o = 16; o; o >>= 1) {
        s  += __shfl_xor_sync(0xffffffffu, s,  o);
        s2 += __shfl_xor_sync(0xffffffffu, s2, o);
    }
    float mu  = s * (1.f / EMB);
    float var = s2 * (1.f / EMB) - mu * mu;
    float inv = rsqrtf(var + 1e-5f);
    float* o_ = out + (size_t)w * EMB;
#pragma unroll
    for (int i = 0; i < 20; i++) {
        int c = lane + 32 * i;
        o_[c] = tf32r((v[i] - mu) * inv * gam[c] + bet[c]);
    }
}

/* ------------------------ weight pre-round (once) -------------------------- */
__global__ void __launch_bounds__(256) round_copy(const float* __restrict__ src,
                                                  float* __restrict__ dst, int n)
{
    int i = blockIdx.x * 256 + threadIdx.x;
    if (i < n) dst[i] = __uint_as_float(f2tf(src[i]));
}

__global__ void __launch_bounds__(256) round_qkv(const float* __restrict__ wq,
        const float* __restrict__ wk, const float* __restrict__ wv)
{
    const int EE = EMB * EMB;
    int i = blockIdx.x * 256 + threadIdx.x;
    if (i >= 3 * EE) return;
    const float* src = (i < EE) ? wq : (i < 2 * EE ? wk : wv);
    int j = i - (i < EE ? 0 : (i < 2 * EE ? EE : 2 * EE));
    g_wqkv[i] = __uint_as_float(f2tf(src[j]));
}

/* ---------------- C = A @ W^T (+bias,res,gelu), TF32 tensor cores ---------- */
template<bool GELU, bool ROUND>
__global__ void __launch_bounds__(256, 2) gemm_tc(const float* __restrict__ A,
        const float* __restrict__ W, const float* __restrict__ bias,
        const float* __restrict__ res, float* __restrict__ C,
        int K, int Nc, int Mtot)
{
    __shared__ unsigned As[3][128][20];
    __shared__ unsigned Bs[3][128][20];

    int tid  = threadIdx.x;
    int warp = tid >> 5, lane = tid & 31;
    int m0 = blockIdx.y * 128, n0 = blockIdx.x * 128;
    int wm = warp & 1, wn = warp >> 1;
    int g  = lane >> 2, t = lane & 3;

    int lr = tid >> 2, lc = tid & 3;
    const float* Ap0 = A + (size_t)(m0 + lr)      * K + lc * 4;
    const float* Ap1 = A + (size_t)(m0 + lr + 64) * K + lc * 4;
    const float* Wp0 = W + (size_t)(n0 + lr)      * K + lc * 4;
    const float* Wp1 = W + (size_t)(n0 + lr + 64) * K + lc * 4;
    bool am0 = (m0 + lr) < Mtot, am1 = (m0 + lr + 64) < Mtot;

    unsigned sA = (unsigned)__cvta_generic_to_shared(As);
    unsigned sB = (unsigned)__cvta_generic_to_shared(Bs);
    unsigned off0 = (lr * 20 + lc * 4) * 4;
    unsigned off1 = ((lr + 64) * 20 + lc * 4) * 4;
    const unsigned BUFB = 128 * 20 * 4;

    float acc[4][4][4];
#pragma unroll
    for (int mi = 0; mi < 4; mi++)
#pragma unroll
        for (int ni = 0; ni < 4; ni++)
#pragma unroll
            for (int e = 0; e < 4; e++) acc[mi][ni][e] = 0.f;

    int nkt = K >> 4;

    auto issue = [&](int kt, int buf) {
        unsigned ba = sA + buf * BUFB, bb = sB + buf * BUFB;
        CP16(ba + off0, Ap0 + kt * 16, am0);
        CP16(ba + off1, Ap1 + kt * 16, am1);
        CP16(bb + off0, Wp0 + kt * 16, 1);
        CP16(bb + off1, Wp1 + kt * 16, 1);
        asm volatile("cp.async.commit_group;");
    };

    issue(0, 0);
    if (nkt > 1) issue(1, 1);

    for (int kt = 0; kt < nkt; kt++) {
        if (kt + 1 < nkt) asm volatile("cp.async.wait_group 1;");
        else              asm volatile("cp.async.wait_group 0;");
        __syncthreads();
        int buf = kt % 3;
#pragma unroll
        for (int ks = 0; ks < 2; ks++) {
            unsigned af[4][4], bf[4][2];
            int kc = ks * 8 + t;
#pragma unroll
            for (int mi = 0; mi < 4; mi++) {
                int r = wm * 64 + mi * 16 + g;
                af[mi][0] = As[buf][r][kc];
                af[mi][1] = As[buf][r + 8][kc];
                af[mi][2] = As[buf][r][kc + 4];
                af[mi][3] = As[buf][r + 8][kc + 4];
            }
#pragma unroll
            for (int ni = 0; ni < 4; ni++) {
                int r = wn * 32 + ni * 8 + g;
                bf[ni][0] = Bs[buf][r][kc];
                bf[ni][1] = Bs[buf][r][kc + 4];
            }
#pragma unroll
            for (int mi = 0; mi < 4; mi++)
#pragma unroll
                for (int ni = 0; ni < 4; ni++)
                    mma_tf32(acc[mi][ni], af[mi], bf[ni]);
        }
        if (kt + 2 < nkt) issue(kt + 2, (kt + 2) % 3);
    }

#pragma unroll
    for (int mi = 0; mi < 4; mi++) {
#pragma unroll
        for (int half = 0; half < 2; half++) {
            int r = m0 + wm * 64 + mi * 16 + g + half * 8;
            if (r >= Mtot) continue;
#pragma unroll
            for (int ni = 0; ni < 4; ni++) {
                int c = n0 + wn * 32 + ni * 8 + 2 * t;
                float vx = acc[mi][ni][half * 2 + 0];
                float vy = acc[mi][ni][half * 2 + 1];
                if (bias) { vx += bias[c]; vy += bias[c + 1]; }
                if (res) {
                    const float* rp = res + (size_t)r * Nc + c;
                    vx += rp[0]; vy += rp[1];
                }
                if (GELU) { vx *= normcdff(vx); vy *= normcdff(vy); }
                if (ROUND) { vx = tf32r(vx); vy = tf32r(vy); }
                float2 out2; out2.x = vx; out2.y = vy;
                *(float2*)(C + (size_t)r * Nc + c) = out2;
            }
        }
    }
}

/* ---------------- qtab[b,n][h][t] = q[b,n,h,:] . rpk_{v|h}[t,:] ------------ */
__global__ void __launch_bounds__(256) qtab_kernel(const float* __restrict__ rpkv,
                                                   const float* __restrict__ rpkh)
{
    __shared__ float qs[EMB];
    __shared__ float tabs[60][65];
    int row = blockIdx.x;
    int tid = threadIdx.x;
    const float* qrow = g_qkv + (size_t)row * QKVS;
    for (int i = tid; i < EMB; i += 256) qs[i] = qrow[i];
    for (int i = tid; i < 1920; i += 256) tabs[i >> 6][i & 63]        = rpkv[i];
    for (int i = tid; i < 1920; i += 256) tabs[30 + (i >> 6)][i & 63] = rpkh[i];
    __syncthreads();
    for (int idx = tid; idx < 600; idx += 256) {
        int h = idx / 60, t = idx - h * 60;
        float s = 0.f;
#pragma unroll
        for (int d = 0; d < 64; d++) s = fmaf(qs[h * 64 + d], tabs[t][d], s);
        g_qtab[(size_t)row * 600 + idx] = s;
    }
}

/* ------------------ rcat TRANSPOSED: g_rcat[d][t] = table[t][d] ------------ */
__global__ void build_rcat(const float* __restrict__ rv, const float* __restrict__ rh)
{
    int i = blockIdx.x * 256 + threadIdx.x;
    if (i >= 64 * 64) return;
    int d = i >> 6, t = i & 63;
    float v = 0.f;
    if (t < 30) v = rv[t * 64 + d];
    else if (t < 60) v = rh[(t - 30) * 64 + d];
    g_rcat[i] = v;
}

/* ------- scores via tf32 MMA: attn = 0.125*(q.k + qtab gathers) ------------ */
__global__ void __launch_bounds__(128) scores_tc()
{
    __shared__ unsigned Qs[64][68];   /* stride 68: 4g+t conflict-free */
    __shared__ unsigned Ks[64][68];
    int bh = blockIdx.z, b = bh / NH, h = bh - b * NH;
    int m0 = blockIdx.x * 64, n0 = blockIdx.y * 64;
    int tid = threadIdx.x, warp = tid >> 5, lane = tid & 31;
    int wm = warp & 1, wn = warp >> 1;
    int g = lane >> 2, t = lane & 3;

    const float* Qb = g_qkv + (size_t)b * SEQ * QKVS + h * HDIM_;
    const float* Kb = Qb + EMB;

    int srow = tid >> 1, shalf = tid & 1;
    bool qok = (n0 + srow) < SEQ, kok = (m0 + srow) < SEQ;
    const float* Qg = Qb + (size_t)(n0 + srow) * QKVS;
    const float* Kg = Kb + (size_t)(m0 + srow) * QKVS;
    float4 z4 = make_float4(0.f, 0.f, 0.f, 0.f);
#pragma unroll
    for (int j = 0; j < 8; j++) {
        int c4 = shalf * 8 + j;
        float4 qv = qok ? *(const float4*)(Qg + c4 * 4) : z4;
        float4 kv = kok ? *(const float4*)(Kg + c4 * 4) : z4;
        uint4 u;
        u.x = f2tf(qv.x); u.y = f2tf(qv.y); u.z = f2tf(qv.z); u.w = f2tf(qv.w);
        *(uint4*)&Qs[srow][c4 * 4] = u;
        u.x = f2tf(kv.x); u.y = f2tf(kv.y); u.z = f2tf(kv.z); u.w = f2tf(kv.w);
        *(uint4*)&Ks[srow][c4 * 4] = u;
    }
    __syncthreads();

    float acc[2][4][4];
#pragma unroll
    for (int mi = 0; mi < 2; mi++)
#pragma unroll
        for (int ni = 0; ni < 4; ni++)
#pragma unroll
            for (int e = 0; e < 4; e++) acc[mi][ni][e] = 0.f;

#pragma unroll
    for (int ks = 0; ks < 8; ks++) {
        int kc = ks * 8 + t;
        unsigned af[2][4], bf[4][2];
#pragma unroll
        for (int mi = 0; mi < 2; mi++) {
            int r = wm * 32 + mi * 16 + g;
            af[mi][0] = Qs[r][kc];     af[mi][1] = Qs[r + 8][kc];
            af[mi][2] = Qs[r][kc + 4]; af[mi][3] = Qs[r + 8][kc + 4];
        }
#pragma unroll
        for (int ni = 0; ni < 4; ni++) {
            int r = wn * 32 + ni * 8 + g;
            bf[ni][0] = Ks[r][kc]; bf[ni][1] = Ks[r][kc + 4];
        }
#pragma unroll
        for (int mi = 0; mi < 2; mi++)
#pragma unroll
            for (int ni = 0; ni < 4; ni++)
                mma_tf32(acc[mi][ni], af[mi], bf[ni]);
    }

#pragma unroll
    for (int mi = 0; mi < 2; mi++) {
#pragma unroll
        for (int half = 0; half < 2; half++) {
            int n = n0 + wm * 32 + mi * 16 + g + half * 8;
            if (n >= SEQ) continue;
            const float* qt = g_qtab + (size_t)(b * SEQ + n) * 600 + h * 60;
            float* arow = g_attn + ((size_t)bh * SEQ + n) * ATTS;
#pragma unroll
            for (int ni = 0; ni < 4; ni++) {
#pragma unroll
                for (int e = 0; e < 2; e++) {
                    int m = m0 + wn * 32 + ni * 8 + 2 * t + e;
                    if (m >= ATTS) continue;
                    float val = 0.f;
                    if (m < SEQ) {
                        int iv, ih; rpe_idx(n, m, iv, ih);
                        val = 0.125f * (acc[mi][ni][half * 2 + e] + qt[iv] + qt[30 + ih]);
                    }
                    arow[m] = val;
                }
            }
        }
    }
}

/* ------------- softmax over m + bin probabilities by (iv, ih) -------------- */
__global__ void __launch_bounds__(256) softmax_kernel()
{
    __shared__ float bins[8][64];
    int wl = threadIdx.x >> 5, lane = threadIdx.x & 31;
    int w = blockIdx.x * 8 + wl;
    if (w >= BHN * SEQ) return;
    int n = w % SEQ;
    float* row = g_attn + (size_t)w * ATTS;

    float e[7]; float mx = -1e30f;
#pragma unroll
    for (int i = 0; i < 7; i++) {
        int m = lane + 32 * i;
        float v = (m < SEQ) ? row[m] : -1e30f;
        e[i] = v; mx = fmaxf(mx, v);
    }
#pragma unroll
    for (int o = 16; o; o >>= 1) mx = fmaxf(mx, __shfl_xor_sync(0xffffffffu, mx, o));
    float s = 0.f;
#pragma unroll
    for (int i = 0; i < 7; i++) {
        int m = lane + 32 * i;
        float ev = (m < SEQ) ? __expf(e[i] - mx) : 0.f;
        e[i] = ev; s += ev;
    }
#pragma unroll
    for (int o = 16; o; o >>= 1) s += __shfl_xor_sync(0xffffffffu, s, o);
    float inv = 1.f / s;

    bins[wl][lane] = 0.f; bins[wl][lane + 32] = 0.f;
    __syncwarp();
#pragma unroll
    for (int i = 0; i < 7; i++) {
        int m = lane + 32 * i;
        if (m < SEQ) {
            float p = e[i] * inv;
            row[m] = p;
            int iv, ih; rpe_idx(n, m, iv, ih);
            atomicAdd(&bins[wl][iv], p);
            atomicAdd(&bins[wl][32 + ih], p);
        }
    }
    __syncwarp();
    float* st = g_stab + (size_t)w * 64;
    for (int t = lane; t < 64; t += 32) {
        float v = (t < 30) ? bins[wl][t] : (t < 60 ? bins[wl][32 + (t - 30)] : 0.f);
        st[t] = v;
    }
}

/* -------- o = P @ V + stab @ rcat via tf32 MMA (5 K-phases of 64) ---------- */
__global__ void __launch_bounds__(128) attnv_tc()
{
    __shared__ unsigned Ps[64][68];
    __shared__ unsigned Vs[64][68];   /* transposed: [d][m_local] */
    int bh = blockIdx.y, b = bh / NH, h = bh - b * NH;
    int n0 = blockIdx.x * 64;
    int tid = threadIdx.x, warp = tid >> 5, lane = tid & 31;
    int wm = warp & 1, wn = warp >> 1;
    int g = lane >> 2, t = lane & 3;

    const float* Pb = g_attn + (size_t)bh * SEQ * ATTS;
    const float* Vb = g_qkv  + (size_t)b * SEQ * QKVS + h * HDIM_ + 2 * EMB;
    const float* Sb = g_stab + (size_t)bh * SEQ * 64;

    int srow = tid >> 1, shalf = tid & 1;
    bool nok = (n0 + srow) < SEQ;
    float4 z4 = make_float4(0.f, 0.f, 0.f, 0.f);

    float acc[2][4][4];
#pragma unroll
    for (int mi = 0; mi < 2; mi++)
#pragma unroll
        for (int ni = 0; ni < 4; ni++)
#pragma unroll
            for (int e = 0; e < 4; e++) acc[mi][ni][e] = 0.f;

    for (int kt = 0; kt < 5; kt++) {
        __syncthreads();
        if (kt < 4) {
            const float* Pg = Pb + (size_t)(n0 + srow) * ATTS + kt * 64;
#pragma unroll
            for (int j = 0; j < 8; j++) {
                int c4 = shalf * 8 + j;
                int mabs = kt * 64 + c4 * 4;
                float4 pv = (nok && mabs + 3 < ATTS) ? *(const float4*)(Pg + c4 * 4) : z4;
                uint4 u;
                u.x = f2tf(pv.x); u.y = f2tf(pv.y); u.z = f2tf(pv.z); u.w = f2tf(pv.w);
                *(uint4*)&Ps[srow][c4 * 4] = u;
            }
            int m = kt * 64 + srow;
            bool vok = m < SEQ;
            const float* Vg = Vb + (size_t)m * QKVS;
#pragma unroll
            for (int j = 0; j < 8; j++) {
                int d4 = shalf * 8 + j;
                float4 vv = vok ? *(const float4*)(Vg + d4 * 4) : z4;
                Vs[d4 * 4 + 0][srow] = f2tf(vv.x);
                Vs[d4 * 4 + 1][srow] = f2tf(vv.y);
                Vs[d4 * 4 + 2][srow] = f2tf(vv.z);
                Vs[d4 * 4 + 3][srow] = f2tf(vv.w);
            }
        } else {
            const float* Sg = Sb + (size_t)(n0 + srow) * 64;
#pragma unroll
            for (int j = 0; j < 8; j++) {
                int c4 = shalf * 8 + j;
                float4 sv = nok ? *(const float4*)(Sg + c4 * 4) : z4;
                uint4 u;
                u.x = f2tf(sv.x); u.y = f2tf(sv.y); u.z = f2tf(sv.z); u.w = f2tf(sv.w);
                *(uint4*)&Ps[srow][c4 * 4] = u;
                float4 rv = *(const float4*)(g_rcat + srow * 64 + c4 * 4);
                u.x = f2tf(rv.x); u.y = f2tf(rv.y); u.z = f2tf(rv.z); u.w = f2tf(rv.w);
                *(uint4*)&Vs[srow][c4 * 4] = u;
            }
        }
        __syncthreads();
#pragma unroll
        for (int ks = 0; ks < 8; ks++) {
            int kc = ks * 8 + t;
            unsigned af[2][4], bf[4][2];
#pragma unroll
            for (int mi = 0; mi < 2; mi++) {
                int r = wm * 32 + mi * 16 + g;
                af[mi][0] = Ps[r][kc];     af[mi][1] = Ps[r + 8][kc];
                af[mi][2] = Ps[r][kc + 4]; af[mi][3] = Ps[r + 8][kc + 4];
            }
#pragma unroll
            for (int ni = 0; ni < 4; ni++) {
                int r = wn * 32 + ni * 8 + g;
                bf[ni][0] = Vs[r][kc]; bf[ni][1] = Vs[r][kc + 4];
            }
#pragma unroll
            for (int mi = 0; mi < 2; mi++)
#pragma unroll
                for (int ni = 0; ni < 4; ni++)
                    mma_tf32(acc[mi][ni], af[mi], bf[ni]);
        }
    }

#pragma unroll
    for (int mi = 0; mi < 2; mi++) {
#pragma unroll
        for (int half = 0; half < 2; half++) {
            int n = n0 + wm * 32 + mi * 16 + g + half * 8;
            if (n >= SEQ) continue;
            float* orow = g_o + (size_t)(b * SEQ + n) * EMB + h * HDIM_;
#pragma unroll
            for (int ni = 0; ni < 4; ni++) {
                int d = wn * 32 + ni * 8 + 2 * t;
                float2 o2;
                o2.x = tf32r(acc[mi][ni][half * 2 + 0]);
                o2.y = tf32r(acc[mi][ni][half * 2 + 1]);
                *(float2*)(orow + d) = o2;
            }
        }
    }
}

/* --------------------------------- launch ---------------------------------- */
extern "C" void kernel_launch(void* const* d_in, const int* in_sizes, int n_in,
                              void* d_out, int out_size)
{
    const float* x     = (const float*)d_in[0];
    const float* ln1_g = (const float*)d_in[1];
    const float* ln1_b = (const float*)d_in[2];
    const float* Wq    = (const float*)d_in[3];
    const float* Wk    = (const float*)d_in[4];
    const float* Wv    = (const float*)d_in[5];
    const float* Wp    = (const float*)d_in[6];
    const float* bp    = (const float*)d_in[7];
    const float* rpk_v = (const float*)d_in[8];
    const float* rpk_h = (const float*)d_in[9];
    const float* rpv_v = (const float*)d_in[10];
    const float* rpv_h = (const float*)d_in[11];
    const float* ln2_g = (const float*)d_in[12];
    const float* ln2_b = (const float*)d_in[13];
    const float* W1    = (const float*)d_in[14];
    const float* b1    = (const float*)d_in[15];
    const float* W2    = (const float*)d_in[16];
    const float* b2    = (const float*)d_in[17];

    float *ph, *pqkv, *po, *px1, *pffn;
    float *pwqkv, *pwp, *pw1, *pw2;
    cudaGetSymbolAddress((void**)&ph,    g_h);
    cudaGetSymbolAddress((void**)&pqkv,  g_qkv);
    cudaGetSymbolAddress((void**)&po,    g_o);
    cudaGetSymbolAddress((void**)&px1,   g_x1);
    cudaGetSymbolAddress((void**)&pffn,  g_ffn);
    cudaGetSymbolAddress((void**)&pwqkv, g_wqkv);
    cudaGetSymbolAddress((void**)&pwp,   g_wp);
    cudaGetSymbolAddress((void**)&pw1,   g_w1);
    cudaGetSymbolAddress((void**)&pw2,   g_w2);

    const int MB = (MROWS + 127) / 128;   /* 99 */
    const int WEE = EMB * EMB, WFE = FF * EMB;

    /* weight pre-rounding (tf32) */
    round_qkv<<<(3 * WEE + 255) / 256, 256>>>(Wq, Wk, Wv);
    round_copy<<<(WEE + 255) / 256, 256>>>(Wp, pwp, WEE);
    round_copy<<<(WFE + 255) / 256, 256>>>(W1, pw1, WFE);
    round_copy<<<(WFE + 255) / 256, 256>>>(W2, pw2, WFE);

    /* LN1 (tf32-rounded output) */
    ln_kernel<<<MROWS / 8, 256>>>(x, ln1_g, ln1_b, ph);
    /* fused QKV projection */
    gemm_tc<false,false><<<dim3(QKVS / 128, MB), 256>>>(ph, pwqkv, nullptr, nullptr, pqkv, EMB, QKVS, MROWS);
    /* RPE precomputes */
    build_rcat<<<16, 256>>>(rpv_v, rpv_h);
    qtab_kernel<<<MROWS, 256>>>(rpk_v, rpk_h);
    /* attention (tensor cores) */
    scores_tc<<<dim3(4, 4, BHN), 128>>>();
    softmax_kernel<<<(BHN * SEQ + 7) / 8, 256>>>();
    attnv_tc<<<dim3(4, BHN), 128>>>();
    /* output projection + residual */
    gemm_tc<false,false><<<dim3(EMB / 128, MB), 256>>>(po, pwp, bp, x, px1, EMB, EMB, MROWS);
    /* FFN block */
    ln_kernel<<<MROWS / 8, 256>>>(px1, ln2_g, ln2_b, ph);
    gemm_tc<true ,true ><<<dim3(FF / 128, MB), 256>>>(ph, pw1, b1, nullptr, pffn, EMB, FF, MROWS);
    gemm_tc<false,false><<<dim3(EMB / 128, MB), 256>>>(pffn, pw2, b2, px1, (float*)d_out, FF, EMB, MROWS);
}

// round 14
// speedup vs baseline: 1.1237x; 1.1143x over previous
#include <cuda_runtime.h>
#include <math.h>

#define BATCH 64
#define SEQ   197
#define EMB   640
#define NH    10
#define HDIM_ 64
#define FF    2560
#define MROWS (BATCH*SEQ)          /* 12608 */
#define ATTS  208                  /* padded attn row stride */
#define BHN   (BATCH*NH)           /* 640 */
#define QKVS  1920                 /* fused qkv row stride */

/* ------------------------- scratch (device globals) ------------------------ */
__device__ float g_h  [MROWS*EMB];
__device__ float g_qkv[(size_t)MROWS*QKVS];     /* [q|k|v] per row */
__device__ float g_o  [MROWS*EMB];
__device__ float g_x1 [MROWS*EMB];
__device__ float g_ffn[(size_t)MROWS*FF];
__device__ float g_attn[(size_t)BHN*SEQ*ATTS];
__device__ float g_qtab[(size_t)MROWS*600];
__device__ float g_stab[(size_t)BHN*SEQ*64];
__device__ float g_rcat[64*64];                 /* [t][d]: [rpv_v;rpv_h;0] */
/* pre-rounded (tf32) weights */
__device__ float g_wqkv[(size_t)QKVS*EMB];      /* [Wq;Wk;Wv] */
__device__ float g_wp[EMB*EMB];
__device__ float g_w1[(size_t)FF*EMB];
__device__ float g_w2[(size_t)FF*EMB];

/* ------------------------------ tf32 helpers ------------------------------- */
__device__ __forceinline__ unsigned f2tf(float f)
{
    unsigned r;
    asm("cvt.rna.tf32.f32 %0, %1;" : "=r"(r) : "f"(f));
    return r;
}
__device__ __forceinline__ float tf32r(float f) { return __uint_as_float(f2tf(f)); }

__device__ __forceinline__ void mma_tf32(float* c, const unsigned* a, const unsigned* b)
{
    asm volatile(
        "mma.sync.aligned.m16n8k8.row.col.f32.tf32.tf32.f32 "
        "{%0,%1,%2,%3},{%4,%5,%6,%7},{%8,%9},{%0,%1,%2,%3};"
        : "+f"(c[0]), "+f"(c[1]), "+f"(c[2]), "+f"(c[3])
        : "r"(a[0]), "r"(a[1]), "r"(a[2]), "r"(a[3]), "r"(b[0]), "r"(b[1]));
}

#define CP16(dst, src, ok) \
    asm volatile("cp.async.cg.shared.global [%0], [%1], 16, %2;" \
        :: "r"(dst), "l"(src), "r"((ok) ? 16 : 0))

/* ------------------------------ rpe indexing ------------------------------- */
__device__ __forceinline__ void rpe_idx(int n, int m, int &iv, int &ih)
{
    if (n == 0 || m == 0) { iv = 0; ih = 0; return; }
    int r = n - 1, c = m - 1;
    int dv = c / 14 - r / 14;
    int dh = c % 14 - r % 14;
    dv = dv < -14 ? -14 : (dv > 14 ? 14 : dv);
    dh = dh < -14 ? -14 : (dh > 14 ? 14 : dh);
    iv = dv + 15; ih = dh + 15;
}

/* -------------------- layer norm (output tf32-rounded) --------------------- */
__global__ void __launch_bounds__(256) ln_kernel(const float* __restrict__ x,
        const float* __restrict__ gam, const float* __restrict__ bet,
        float* __restrict__ out)
{
    int w    = (blockIdx.x * blockDim.x + threadIdx.x) >> 5;
    int lane = threadIdx.x & 31;
    if (w >= MROWS) return;
    const float* r = x + (size_t)w * EMB;
    float v[20]; float s = 0.f, s2 = 0.f;
#pragma unroll
    for (int i = 0; i < 20; i++) {
        float t = r[lane + 32 * i]; v[i] = t; s += t; s2 += t * t;
    }
#pragma unroll
    for (int o = 16; o; o >>= 1) {
        s  += __shfl_xor_sync(0xffffffffu, s,  o);
        s2 += __shfl_xor_sync(0xffffffffu, s2, o);
    }
    float mu  = s * (1.f / EMB);
    float var = s2 * (1.f / EMB) - mu * mu;
    float inv = rsqrtf(var + 1e-5f);
    float* o_ = out + (size_t)w * EMB;
#pragma unroll
    for (int i = 0; i < 20; i++) {
        int c = lane + 32 * i;
        o_[c] = tf32r((v[i] - mu) * inv * gam[c] + bet[c]);
    }
}

/* ------------------------ weight pre-round (once) -------------------------- */
__global__ void __launch_bounds__(256) round_copy(const float* __restrict__ src,
                                                  float* __restrict__ dst, int n)
{
    int i = blockIdx.x * 256 + threadIdx.x;
    if (i < n) dst[i] = __uint_as_float(f2tf(src[i]));
}

__global__ void __launch_bounds__(256) round_qkv(const float* __restrict__ wq,
        const float* __restrict__ wk, const float* __restrict__ wv)
{
    const int EE = EMB * EMB;
    int i = blockIdx.x * 256 + threadIdx.x;
    if (i >= 3 * EE) return;
    const float* src = (i < EE) ? wq : (i < 2 * EE ? wk : wv);
    int j = i - (i < EE ? 0 : (i < 2 * EE ? EE : 2 * EE));
    g_wqkv[i] = __uint_as_float(f2tf(src[j]));
}

/* ---------------- C = A @ W^T (+bias,res,gelu), TF32 tensor cores ----------
 * A:[Mtot,K], W:[Nc,K], pre-rounded tf32. K%32==0, Nc%128==0.
 * Block 128x128, 8 warps (2x4), warp tile 64x32, K-tile 32,
 * cp.async 3-stage ring, 1 barrier / K-tile.                               */
template<bool GELU, bool ROUND>
__global__ void __launch_bounds__(256, 2) gemm_tc(const float* __restrict__ A,
        const float* __restrict__ W, const float* __restrict__ bias,
        const float* __restrict__ res, float* __restrict__ C,
        int K, int Nc, int Mtot)
{
    __shared__ unsigned As[3][128][36];   /* stride 36: 4g+t conflict-free */
    __shared__ unsigned Bs[3][128][36];

    int tid  = threadIdx.x;
    int warp = tid >> 5, lane = tid & 31;
    int m0 = blockIdx.y * 128, n0 = blockIdx.x * 128;
    int wm = warp & 1, wn = warp >> 1;          /* 2 (M) x 4 (N) warps */
    int g  = lane >> 2, t = lane & 3;

    /* staging: row = tid>>3 (0..31), sub = tid&7 (16B chunk of 32-float row) */
    int srow = tid >> 3, sub = tid & 7;
    const float* Ap[4]; const float* Wp[4]; bool am[4];
    unsigned offj[4];
#pragma unroll
    for (int j = 0; j < 4; j++) {
        int row = srow + 32 * j;
        Ap[j] = A + (size_t)(m0 + row) * K + sub * 4;
        Wp[j] = W + (size_t)(n0 + row) * K + sub * 4;
        am[j] = (m0 + row) < Mtot;
        offj[j] = (row * 36 + sub * 4) * 4;
    }
    unsigned sA = (unsigned)__cvta_generic_to_shared(As);
    unsigned sB = (unsigned)__cvta_generic_to_shared(Bs);
    const unsigned BUFB = 128 * 36 * 4;

    float acc[4][4][4];
#pragma unroll
    for (int mi = 0; mi < 4; mi++)
#pragma unroll
        for (int ni = 0; ni < 4; ni++)
#pragma unroll
            for (int e = 0; e < 4; e++) acc[mi][ni][e] = 0.f;

    int nkt = K >> 5;

    auto issue = [&](int kt, int buf) {
        unsigned ba = sA + buf * BUFB, bb = sB + buf * BUFB;
#pragma unroll
        for (int j = 0; j < 4; j++) {
            CP16(ba + offj[j], Ap[j] + kt * 32, am[j]);
            CP16(bb + offj[j], Wp[j] + kt * 32, 1);
        }
        asm volatile("cp.async.commit_group;");
    };

    issue(0, 0);
    if (nkt > 1) issue(1, 1);

    for (int kt = 0; kt < nkt; kt++) {
        if (kt + 1 < nkt) asm volatile("cp.async.wait_group 1;");
        else              asm volatile("cp.async.wait_group 0;");
        __syncthreads();
        int buf = kt % 3;
#pragma unroll
        for (int ks = 0; ks < 4; ks++) {
            unsigned af[4][4], bf[4][2];
            int kc = ks * 8 + t;
#pragma unroll
            for (int mi = 0; mi < 4; mi++) {
                int r = wm * 64 + mi * 16 + g;
                af[mi][0] = As[buf][r][kc];
                af[mi][1] = As[buf][r + 8][kc];
                af[mi][2] = As[buf][r][kc + 4];
                af[mi][3] = As[buf][r + 8][kc + 4];
            }
#pragma unroll
            for (int ni = 0; ni < 4; ni++) {
                int r = wn * 32 + ni * 8 + g;
                bf[ni][0] = Bs[buf][r][kc];
                bf[ni][1] = Bs[buf][r][kc + 4];
            }
#pragma unroll
            for (int mi = 0; mi < 4; mi++)
#pragma unroll
                for (int ni = 0; ni < 4; ni++)
                    mma_tf32(acc[mi][ni], af[mi], bf[ni]);
        }
        if (kt + 2 < nkt) issue(kt + 2, (kt + 2) % 3);
    }

    /* epilogue */
#pragma unroll
    for (int mi = 0; mi < 4; mi++) {
#pragma unroll
        for (int half = 0; half < 2; half++) {
            int r = m0 + wm * 64 + mi * 16 + g + half * 8;
            if (r >= Mtot) continue;
#pragma unroll
            for (int ni = 0; ni < 4; ni++) {
                int c = n0 + wn * 32 + ni * 8 + 2 * t;
                float vx = acc[mi][ni][half * 2 + 0];
                float vy = acc[mi][ni][half * 2 + 1];
                if (bias) { vx += bias[c]; vy += bias[c + 1]; }
                if (res) {
                    const float* rp = res + (size_t)r * Nc + c;
                    vx += rp[0]; vy += rp[1];
                }
                if (GELU) { vx *= normcdff(vx); vy *= normcdff(vy); }
                if (ROUND) { vx = tf32r(vx); vy = tf32r(vy); }
                float2 out2; out2.x = vx; out2.y = vy;
                *(float2*)(C + (size_t)r * Nc + c) = out2;
            }
        }
    }
}

/* ---------------- qtab[b,n][h][t] = q[b,n,h,:] . rpk_{v|h}[t,:] ------------ */
__global__ void __launch_bounds__(256) qtab_kernel(const float* __restrict__ rpkv,
                                                   const float* __restrict__ rpkh)
{
    __shared__ float qs[EMB];
    __shared__ float tabs[60][65];
    int row = blockIdx.x;
    int tid = threadIdx.x;
    const float* qrow = g_qkv + (size_t)row * QKVS;
    for (int i = tid; i < EMB; i += 256) qs[i] = qrow[i];
    for (int i = tid; i < 1920; i += 256) tabs[i >> 6][i & 63]        = rpkv[i];
    for (int i = tid; i < 1920; i += 256) tabs[30 + (i >> 6)][i & 63] = rpkh[i];
    __syncthreads();
    for (int idx = tid; idx < 600; idx += 256) {
        int h = idx / 60, t = idx - h * 60;
        float s = 0.f;
#pragma unroll
        for (int d = 0; d < 64; d++) s = fmaf(qs[h * 64 + d], tabs[t][d], s);
        g_qtab[(size_t)row * 600 + idx] = s;
    }
}

/* ------------------------ rcat = [rpv_v ; rpv_h ; 0] (t-major) ------------- */
__global__ void build_rcat(const float* __restrict__ rv, const float* __restrict__ rh)
{
    int i = blockIdx.x * 256 + threadIdx.x;
    if (i >= 64 * 64) return;
    int t = i >> 6, d = i & 63;
    float v = 0.f;
    if (t < 30) v = rv[t * 64 + d];
    else if (t < 60) v = rh[(t - 30) * 64 + d];
    g_rcat[i] = v;
}

/* ------------- attn[b,h,n,m] = 0.125*(q.k + qtab[iv] + qtab[30+ih]) -------- */
__global__ void __launch_bounds__(256) scores_kernel()
{
    __shared__ float Qs[16][68];
    __shared__ float Ks[16][68];
    int bh = blockIdx.z, b = bh / NH, h = bh - b * NH;
    int m0 = blockIdx.x * 64, n0 = blockIdx.y * 64;
    int tid = threadIdx.x;
    int lr = tid >> 2, kg = tid & 3;
    int tx = tid & 15, ty = tid >> 4;
    const float* Qb = g_qkv + (size_t)b * SEQ * QKVS + h * HDIM_;
    const float* Kb = Qb + EMB;
    bool qok = (n0 + lr) < SEQ, kok = (m0 + lr) < SEQ;
    float acc[4][4];
#pragma unroll
    for (int i = 0; i < 4; i++)
#pragma unroll
        for (int j = 0; j < 4; j++) acc[i][j] = 0.f;

    for (int kt = 0; kt < 4; kt++) {
        float4 qv = make_float4(0.f,0.f,0.f,0.f), kv = make_float4(0.f,0.f,0.f,0.f);
        if (qok) qv = *(const float4*)(Qb + (size_t)(n0 + lr) * QKVS + kt * 16 + kg * 4);
        if (kok) kv = *(const float4*)(Kb + (size_t)(m0 + lr) * QKVS + kt * 16 + kg * 4);
        __syncthreads();
        Qs[kg*4+0][lr] = qv.x; Qs[kg*4+1][lr] = qv.y;
        Qs[kg*4+2][lr] = qv.z; Qs[kg*4+3][lr] = qv.w;
        Ks[kg*4+0][lr] = kv.x; Ks[kg*4+1][lr] = kv.y;
        Ks[kg*4+2][lr] = kv.z; Ks[kg*4+3][lr] = kv.w;
        __syncthreads();
#pragma unroll
        for (int k = 0; k < 16; k++) {
            float4 a = *(const float4*)&Qs[k][ty * 4];
            float4 c = *(const float4*)&Ks[k][tx * 4];
            float aa[4] = {a.x, a.y, a.z, a.w};
            float cc[4] = {c.x, c.y, c.z, c.w};
#pragma unroll
            for (int i = 0; i < 4; i++)
#pragma unroll
                for (int j = 0; j < 4; j++)
                    acc[i][j] = fmaf(aa[i], cc[j], acc[i][j]);
        }
    }

    float* arow = g_attn + (size_t)bh * SEQ * ATTS;
#pragma unroll
    for (int i = 0; i < 4; i++) {
        int n = n0 + ty * 4 + i;
        if (n >= SEQ) continue;
        const float* qt = g_qtab + (size_t)(b * SEQ + n) * 600 + h * 60;
#pragma unroll
        for (int j = 0; j < 4; j++) {
            int m = m0 + tx * 4 + j;
            if (m >= ATTS) continue;
            float val = 0.f;
            if (m < SEQ) {
                int iv, ih; rpe_idx(n, m, iv, ih);
                val = 0.125f * (acc[i][j] + qt[iv] + qt[30 + ih]);
            }
            arow[(size_t)n * ATTS + m] = val;
        }
    }
}

/* ------------- softmax over m + bin probabilities by (iv, ih) -------------- */
__global__ void __launch_bounds__(256) softmax_kernel()
{
    __shared__ float bins[8][64];
    int wl = threadIdx.x >> 5, lane = threadIdx.x & 31;
    int w = blockIdx.x * 8 + wl;
    if (w >= BHN * SEQ) return;
    int n = w % SEQ;
    float* row = g_attn + (size_t)w * ATTS;

    float e[7]; float mx = -1e30f;
#pragma unroll
    for (int i = 0; i < 7; i++) {
        int m = lane + 32 * i;
        float v = (m < SEQ) ? row[m] : -1e30f;
        e[i] = v; mx = fmaxf(mx, v);
    }
#pragma unroll
    for (int o = 16; o; o >>= 1) mx = fmaxf(mx, __shfl_xor_sync(0xffffffffu, mx, o));
    float s = 0.f;
#pragma unroll
    for (int i = 0; i < 7; i++) {
        int m = lane + 32 * i;
        float ev = (m < SEQ) ? __expf(e[i] - mx) : 0.f;
        e[i] = ev; s += ev;
    }
#pragma unroll
    for (int o = 16; o; o >>= 1) s += __shfl_xor_sync(0xffffffffu, s, o);
    float inv = 1.f / s;

    bins[wl][lane] = 0.f; bins[wl][lane + 32] = 0.f;
    __syncwarp();
#pragma unroll
    for (int i = 0; i < 7; i++) {
        int m = lane + 32 * i;
        if (m < SEQ) {
            float p = e[i] * inv;
            row[m] = p;
            int iv, ih; rpe_idx(n, m, iv, ih);
            atomicAdd(&bins[wl][iv], p);
            atomicAdd(&bins[wl][32 + ih], p);
        }
    }
    __syncwarp();
    float* st = g_stab + (size_t)w * 64;
    for (int t = lane; t < 64; t += 32) {
        float v = (t < 30) ? bins[wl][t] : (t < 60 ? bins[wl][32 + (t - 30)] : 0.f);
        st[t] = v;
    }
}

/* -------- o[b,h,n,:] = P @ V  +  stab @ rcat  (two K-phases, 64x64) -------- */
__global__ void __launch_bounds__(256) attnv_kernel()
{
    __shared__ float As[16][68];
    __shared__ float Bs[16][68];
    int bh = blockIdx.y, b = bh / NH, h = bh - b * NH;
    int n0 = blockIdx.x * 64;
    int tid = threadIdx.x;
    int lr = tid >> 2, kg = tid & 3;
    int kl = tid >> 4, dg = tid & 15;
    int tx = tid & 15, ty = tid >> 4;
    const float* Pb = g_attn + (size_t)bh * SEQ * ATTS;
    const float* Vb = g_qkv  + (size_t)b * SEQ * QKVS + h * HDIM_ + 2 * EMB;
    const float* Sb = g_stab + (size_t)bh * SEQ * 64;
    bool aok = (n0 + lr) < SEQ;

    float acc[4][4];
#pragma unroll
    for (int i = 0; i < 4; i++)
#pragma unroll
        for (int j = 0; j < 4; j++) acc[i][j] = 0.f;

    for (int kt = 0; kt < 13; kt++) {
        float4 av = make_float4(0.f,0.f,0.f,0.f);
        if (aok) av = *(const float4*)(Pb + (size_t)(n0 + lr) * ATTS + kt * 16 + kg * 4);
        int mB = kt * 16 + kl;
        float4 bv = make_float4(0.f,0.f,0.f,0.f);
        if (mB < SEQ) bv = *(const float4*)(Vb + (size_t)mB * QKVS + dg * 4);
        __syncthreads();
        As[kg*4+0][lr] = av.x; As[kg*4+1][lr] = av.y;
        As[kg*4+2][lr] = av.z; As[kg*4+3][lr] = av.w;
        *(float4*)&Bs[kl][dg * 4] = bv;
        __syncthreads();
#pragma unroll
        for (int k = 0; k < 16; k++) {
            float4 a = *(const float4*)&As[k][ty * 4];
            float4 c = *(const float4*)&Bs[k][tx * 4];
            float aa[4] = {a.x, a.y, a.z, a.w};
            float cc[4] = {c.x, c.y, c.z, c.w};
#pragma unroll
            for (int i = 0; i < 4; i++)
#pragma unroll
                for (int j = 0; j < 4; j++)
                    acc[i][j] = fmaf(aa[i], cc[j], acc[i][j]);
        }
    }
    for (int kt = 0; kt < 4; kt++) {
        float4 av = make_float4(0.f,0.f,0.f,0.f);
        if (aok) av = *(const float4*)(Sb + (size_t)(n0 + lr) * 64 + kt * 16 + kg * 4);
        float4 bv = *(const float4*)(g_rcat + (kt * 16 + kl) * 64 + dg * 4);
        __syncthreads();
        As[kg*4+0][lr] = av.x; As[kg*4+1][lr] = av.y;
        As[kg*4+2][lr] = av.z; As[kg*4+3][lr] = av.w;
        *(float4*)&Bs[kl][dg * 4] = bv;
        __syncthreads();
#pragma unroll
        for (int k = 0; k < 16; k++) {
            float4 a = *(const float4*)&As[k][ty * 4];
            float4 c = *(const float4*)&Bs[k][tx * 4];
            float aa[4] = {a.x, a.y, a.z, a.w};
            float cc[4] = {c.x, c.y, c.z, c.w};
#pragma unroll
            for (int i = 0; i < 4; i++)
#pragma unroll
                for (int j = 0; j < 4; j++)
                    acc[i][j] = fmaf(aa[i], cc[j], acc[i][j]);
        }
    }

#pragma unroll
    for (int i = 0; i < 4; i++) {
        int n = n0 + ty * 4 + i;
        if (n >= SEQ) continue;
        float4 vv;
        vv.x = tf32r(acc[i][0]); vv.y = tf32r(acc[i][1]);
        vv.z = tf32r(acc[i][2]); vv.w = tf32r(acc[i][3]);
        *(float4*)(g_o + (size_t)(b * SEQ + n) * EMB + h * HDIM_ + tx * 4) = vv;
    }
}

/* --------------------------------- launch ---------------------------------- */
extern "C" void kernel_launch(void* const* d_in, const int* in_sizes, int n_in,
                              void* d_out, int out_size)
{
    const float* x     = (const float*)d_in[0];
    const float* ln1_g = (const float*)d_in[1];
    const float* ln1_b = (const float*)d_in[2];
    const float* Wq    = (const float*)d_in[3];
    const float* Wk    = (const float*)d_in[4];
    const float* Wv    = (const float*)d_in[5];
    const float* Wp    = (const float*)d_in[6];
    const float* bp    = (const float*)d_in[7];
    const float* rpk_v = (const float*)d_in[8];
    const float* rpk_h = (const float*)d_in[9];
    const float* rpv_v = (const float*)d_in[10];
    const float* rpv_h = (const float*)d_in[11];
    const float* ln2_g = (const float*)d_in[12];
    const float* ln2_b = (const float*)d_in[13];
    const float* W1    = (const float*)d_in[14];
    const float* b1    = (const float*)d_in[15];
    const float* W2    = (const float*)d_in[16];
    const float* b2    = (const float*)d_in[17];

    float *ph, *pqkv, *po, *px1, *pffn;
    float *pwqkv, *pwp, *pw1, *pw2;
    cudaGetSymbolAddress((void**)&ph,    g_h);
    cudaGetSymbolAddress((void**)&pqkv,  g_qkv);
    cudaGetSymbolAddress((void**)&po,    g_o);
    cudaGetSymbolAddress((void**)&px1,   g_x1);
    cudaGetSymbolAddress((void**)&pffn,  g_ffn);
    cudaGetSymbolAddress((void**)&pwqkv, g_wqkv);
    cudaGetSymbolAddress((void**)&pwp,   g_wp);
    cudaGetSymbolAddress((void**)&pw1,   g_w1);
    cudaGetSymbolAddress((void**)&pw2,   g_w2);

    const int MB = (MROWS + 127) / 128;   /* 99 */
    const int WEE = EMB * EMB, WFE = FF * EMB;

    /* weight pre-rounding (tf32) */
    round_qkv<<<(3 * WEE + 255) / 256, 256>>>(Wq, Wk, Wv);
    round_copy<<<(WEE + 255) / 256, 256>>>(Wp, pwp, WEE);
    round_copy<<<(WFE + 255) / 256, 256>>>(W1, pw1, WFE);
    round_copy<<<(WFE + 255) / 256, 256>>>(W2, pw2, WFE);

    /* LN1 (tf32-rounded output) */
    ln_kernel<<<MROWS / 8, 256>>>(x, ln1_g, ln1_b, ph);
    /* fused QKV projection */
    gemm_tc<false,false><<<dim3(QKVS / 128, MB), 256>>>(ph, pwqkv, nullptr, nullptr, pqkv, EMB, QKVS, MROWS);
    /* RPE precomputes */
    build_rcat<<<16, 256>>>(rpv_v, rpv_h);
    qtab_kernel<<<MROWS, 256>>>(rpk_v, rpk_h);
    /* attention (SIMT — best known config) */
    scores_kernel<<<dim3(4, 4, BHN), 256>>>();
    softmax_kernel<<<(BHN * SEQ + 7) / 8, 256>>>();
    attnv_kernel<<<dim3(4, BHN), 256>>>();
    /* output projection + residual */
    gemm_tc<false,false><<<dim3(EMB / 128, MB), 256>>>(po, pwp, bp, x, px1, EMB, EMB, MROWS);
    /* FFN block */
    ln_kernel<<<MROWS / 8, 256>>>(px1, ln2_g, ln2_b, ph);
    gemm_tc<true ,true ><<<dim3(FF / 128, MB), 256>>>(ph, pw1, b1, nullptr, pffn, EMB, FF, MROWS);
    gemm_tc<false,false><<<dim3(EMB / 128, MB), 256>>>(pffn, pw2, b2, px1, (float*)d_out, FF, EMB, MROWS);
}

// round 15
// speedup vs baseline: 1.1252x; 1.0013x over previous
#include <cuda_runtime.h>
#include <math.h>

#define BATCH 64
#define SEQ   197
#define EMB   640
#define NH    10
#define HDIM_ 64
#define FF    2560
#define MROWS (BATCH*SEQ)          /* 12608 */
#define ATTS  208                  /* padded attn row stride */
#define BHN   (BATCH*NH)           /* 640 */
#define QKVS  1920                 /* fused qkv row stride */

/* ------------------------- scratch (device globals) ------------------------ */
__device__ float g_h  [MROWS*EMB];
__device__ float g_qkv[(size_t)MROWS*QKVS];     /* [q|k|v] per row */
__device__ float g_o  [MROWS*EMB];
__device__ float g_x1 [MROWS*EMB];
__device__ float g_ffn[(size_t)MROWS*FF];
__device__ float g_attn[(size_t)BHN*SEQ*ATTS];
__device__ float g_qtab[(size_t)MROWS*600];
__device__ float g_stab[(size_t)BHN*SEQ*64];
__device__ float g_rcat[64*64];                 /* [t][d]: [rpv_v;rpv_h;0] */
/* pre-rounded (tf32) weights */
__device__ float g_wqkv[(size_t)QKVS*EMB];      /* [Wq;Wk;Wv] */
__device__ float g_wp[EMB*EMB];
__device__ float g_w1[(size_t)FF*EMB];
__device__ float g_w2[(size_t)FF*EMB];

/* ------------------------------ tf32 helpers ------------------------------- */
__device__ __forceinline__ unsigned f2tf(float f)
{
    unsigned r;
    asm("cvt.rna.tf32.f32 %0, %1;" : "=r"(r) : "f"(f));
    return r;
}
__device__ __forceinline__ float tf32r(float f) { return __uint_as_float(f2tf(f)); }

__device__ __forceinline__ void mma_tf32(float* c, const unsigned* a, const unsigned* b)
{
    asm volatile(
        "mma.sync.aligned.m16n8k8.row.col.f32.tf32.tf32.f32 "
        "{%0,%1,%2,%3},{%4,%5,%6,%7},{%8,%9},{%0,%1,%2,%3};"
        : "+f"(c[0]), "+f"(c[1]), "+f"(c[2]), "+f"(c[3])
        : "r"(a[0]), "r"(a[1]), "r"(a[2]), "r"(a[3]), "r"(b[0]), "r"(b[1]));
}

#define CP16(dst, src, ok) \
    asm volatile("cp.async.cg.shared.global [%0], [%1], 16, %2;" \
        :: "r"(dst), "l"(src), "r"((ok) ? 16 : 0))

/* ------------------------------ rpe indexing ------------------------------- */
__device__ __forceinline__ void rpe_idx(int n, int m, int &iv, int &ih)
{
    if (n == 0 || m == 0) { iv = 0; ih = 0; return; }
    int r = n - 1, c = m - 1;
    int dv = c / 14 - r / 14;
    int dh = c % 14 - r % 14;
    dv = dv < -14 ? -14 : (dv > 14 ? 14 : dv);
    dh = dh < -14 ? -14 : (dh > 14 ? 14 : dh);
    iv = dv + 15; ih = dh + 15;
}

/* -------------------- layer norm (output tf32-rounded) --------------------- */
__global__ void __launch_bounds__(256) ln_kernel(const float* __restrict__ x,
        const float* __restrict__ gam, const float* __restrict__ bet,
        float* __restrict__ out)
{
    int w    = (blockIdx.x * blockDim.x + threadIdx.x) >> 5;
    int lane = threadIdx.x & 31;
    if (w >= MROWS) return;
    const float* r = x + (size_t)w * EMB;
    float v[20]; float s = 0.f, s2 = 0.f;
#pragma unroll
    for (int i = 0; i < 20; i++) {
        float t = r[lane + 32 * i]; v[i] = t; s += t; s2 += t * t;
    }
#pragma unroll
    for (int o = 16; o; o >>= 1) {
        s  += __shfl_xor_sync(0xffffffffu, s,  o);
        s2 += __shfl_xor_sync(0xffffffffu, s2, o);
    }
    float mu  = s * (1.f / EMB);
    float var = s2 * (1.f / EMB) - mu * mu;
    float inv = rsqrtf(var + 1e-5f);
    float* o_ = out + (size_t)w * EMB;
#pragma unroll
    for (int i = 0; i < 20; i++) {
        int c = lane + 32 * i;
        o_[c] = tf32r((v[i] - mu) * inv * gam[c] + bet[c]);
    }
}

/* ------------------------ weight pre-round (once) -------------------------- */
__global__ void __launch_bounds__(256) round_copy(const float* __restrict__ src,
                                                  float* __restrict__ dst, int n)
{
    int i = blockIdx.x * 256 + threadIdx.x;
    if (i < n) dst[i] = __uint_as_float(f2tf(src[i]));
}

__global__ void __launch_bounds__(256) round_qkv(const float* __restrict__ wq,
        const float* __restrict__ wk, const float* __restrict__ wv)
{
    const int EE = EMB * EMB;
    int i = blockIdx.x * 256 + threadIdx.x;
    if (i >= 3 * EE) return;
    const float* src = (i < EE) ? wq : (i < 2 * EE ? wk : wv);
    int j = i - (i < EE ? 0 : (i < 2 * EE ? EE : 2 * EE));
    g_wqkv[i] = __uint_as_float(f2tf(src[j]));
}

/* ---------------- C = A @ W^T (+bias,res,gelu), TF32 tensor cores ----------
 * A:[Mtot,K], W:[Nc,K], pre-rounded tf32. K%32==0, Nc%128==0.
 * Block 128x128, 8 warps (2x4), warp tile 64x32, K-tile 32,
 * cp.async 3-stage ring, 1 barrier / K-tile.                               */
template<bool GELU, bool ROUND>
__global__ void __launch_bounds__(256, 2) gemm_tc(const float* __restrict__ A,
        const float* __restrict__ W, const float* __restrict__ bias,
        const float* __restrict__ res, float* __restrict__ C,
        int K, int Nc, int Mtot)
{
    __shared__ unsigned As[3][128][36];   /* stride 36: 4g+t conflict-free */
    __shared__ unsigned Bs[3][128][36];

    int tid  = threadIdx.x;
    int warp = tid >> 5, lane = tid & 31;
    int m0 = blockIdx.y * 128, n0 = blockIdx.x * 128;
    int wm = warp & 1, wn = warp >> 1;          /* 2 (M) x 4 (N) warps */
    int g  = lane >> 2, t = lane & 3;

    /* staging: row = tid>>3 (0..31), sub = tid&7 (16B chunk of 32-float row) */
    int srow = tid >> 3, sub = tid & 7;
    const float* Ap[4]; const float* Wp[4]; bool am[4];
    unsigned offj[4];
#pragma unroll
    for (int j = 0; j < 4; j++) {
        int row = srow + 32 * j;
        Ap[j] = A + (size_t)(m0 + row) * K + sub * 4;
        Wp[j] = W + (size_t)(n0 + row) * K + sub * 4;
        am[j] = (m0 + row) < Mtot;
        offj[j] = (row * 36 + sub * 4) * 4;
    }
    unsigned sA = (unsigned)__cvta_generic_to_shared(As);
    unsigned sB = (unsigned)__cvta_generic_to_shared(Bs);
    const unsigned BUFB = 128 * 36 * 4;

    float acc[4][4][4];
#pragma unroll
    for (int mi = 0; mi < 4; mi++)
#pragma unroll
        for (int ni = 0; ni < 4; ni++)
#pragma unroll
            for (int e = 0; e < 4; e++) acc[mi][ni][e] = 0.f;

    int nkt = K >> 5;

    auto issue = [&](int kt, int buf) {
        unsigned ba = sA + buf * BUFB, bb = sB + buf * BUFB;
#pragma unroll
        for (int j = 0; j < 4; j++) {
            CP16(ba + offj[j], Ap[j] + kt * 32, am[j]);
            CP16(bb + offj[j], Wp[j] + kt * 32, 1);
        }
        asm volatile("cp.async.commit_group;");
    };

    issue(0, 0);
    if (nkt > 1) issue(1, 1);

    for (int kt = 0; kt < nkt; kt++) {
        if (kt + 1 < nkt) asm volatile("cp.async.wait_group 1;");
        else              asm volatile("cp.async.wait_group 0;");
        __syncthreads();
        int buf = kt % 3;
#pragma unroll
        for (int ks = 0; ks < 4; ks++) {
            unsigned af[4][4], bf[4][2];
            int kc = ks * 8 + t;
#pragma unroll
            for (int mi = 0; mi < 4; mi++) {
                int r = wm * 64 + mi * 16 + g;
                af[mi][0] = As[buf][r][kc];
                af[mi][1] = As[buf][r + 8][kc];
                af[mi][2] = As[buf][r][kc + 4];
                af[mi][3] = As[buf][r + 8][kc + 4];
            }
#pragma unroll
            for (int ni = 0; ni < 4; ni++) {
                int r = wn * 32 + ni * 8 + g;
                bf[ni][0] = Bs[buf][r][kc];
                bf[ni][1] = Bs[buf][r][kc + 4];
            }
#pragma unroll
            for (int mi = 0; mi < 4; mi++)
#pragma unroll
                for (int ni = 0; ni < 4; ni++)
                    mma_tf32(acc[mi][ni], af[mi], bf[ni]);
        }
        if (kt + 2 < nkt) issue(kt + 2, (kt + 2) % 3);
    }

    /* epilogue */
#pragma unroll
    for (int mi = 0; mi < 4; mi++) {
#pragma unroll
        for (int half = 0; half < 2; half++) {
            int r = m0 + wm * 64 + mi * 16 + g + half * 8;
            if (r >= Mtot) continue;
#pragma unroll
            for (int ni = 0; ni < 4; ni++) {
                int c = n0 + wn * 32 + ni * 8 + 2 * t;
                float vx = acc[mi][ni][half * 2 + 0];
                float vy = acc[mi][ni][half * 2 + 1];
                if (bias) { vx += bias[c]; vy += bias[c + 1]; }
                if (res) {
                    const float* rp = res + (size_t)r * Nc + c;
                    vx += rp[0]; vy += rp[1];
                }
                if (GELU) { vx *= normcdff(vx); vy *= normcdff(vy); }
                if (ROUND) { vx = tf32r(vx); vy = tf32r(vy); }
                float2 out2; out2.x = vx; out2.y = vy;
                *(float2*)(C + (size_t)r * Nc + c) = out2;
            }
        }
    }
}

/* ---------------- qtab[b,n][h][t] = q[b,n,h,:] . rpk_{v|h}[t,:] ------------ */
__global__ void __launch_bounds__(256) qtab_kernel(const float* __restrict__ rpkv,
                                                   const float* __restrict__ rpkh)
{
    __shared__ float qs[EMB];
    __shared__ float tabs[60][65];
    int row = blockIdx.x;
    int tid = threadIdx.x;
    const float* qrow = g_qkv + (size_t)row * QKVS;
    for (int i = tid; i < EMB; i += 256) qs[i] = qrow[i];
    for (int i = tid; i < 1920; i += 256) tabs[i >> 6][i & 63]        = rpkv[i];
    for (int i = tid; i < 1920; i += 256) tabs[30 + (i >> 6)][i & 63] = rpkh[i];
    __syncthreads();
    for (int idx = tid; idx < 600; idx += 256) {
        int h = idx / 60, t = idx - h * 60;
        float s = 0.f;
#pragma unroll
        for (int d = 0; d < 64; d++) s = fmaf(qs[h * 64 + d], tabs[t][d], s);
        g_qtab[(size_t)row * 600 + idx] = s;
    }
}

/* ------------------------ rcat = [rpv_v ; rpv_h ; 0] (t-major) ------------- */
__global__ void build_rcat(const float* __restrict__ rv, const float* __restrict__ rh)
{
    int i = blockIdx.x * 256 + threadIdx.x;
    if (i >= 64 * 64) return;
    int t = i >> 6, d = i & 63;
    float v = 0.f;
    if (t < 30) v = rv[t * 64 + d];
    else if (t < 60) v = rh[(t - 30) * 64 + d];
    g_rcat[i] = v;
}

/* ------------- attn[b,h,n,m] = 0.125*(q.k + qtab[iv] + qtab[30+ih]) -------- */
__global__ void __launch_bounds__(256) scores_kernel()
{
    __shared__ float Qs[16][68];
    __shared__ float Ks[16][68];
    int bh = blockIdx.z, b = bh / NH, h = bh - b * NH;
    int m0 = blockIdx.x * 64, n0 = blockIdx.y * 64;
    int tid = threadIdx.x;
    int lr = tid >> 2, kg = tid & 3;
    int tx = tid & 15, ty = tid >> 4;
    const float* Qb = g_qkv + (size_t)b * SEQ * QKVS + h * HDIM_;
    const float* Kb = Qb + EMB;
    bool qok = (n0 + lr) < SEQ, kok = (m0 + lr) < SEQ;
    float acc[4][4];
#pragma unroll
    for (int i = 0; i < 4; i++)
#pragma unroll
        for (int j = 0; j < 4; j++) acc[i][j] = 0.f;

    for (int kt = 0; kt < 4; kt++) {
        float4 qv = make_float4(0.f,0.f,0.f,0.f), kv = make_float4(0.f,0.f,0.f,0.f);
        if (qok) qv = *(const float4*)(Qb + (size_t)(n0 + lr) * QKVS + kt * 16 + kg * 4);
        if (kok) kv = *(const float4*)(Kb + (size_t)(m0 + lr) * QKVS + kt * 16 + kg * 4);
        __syncthreads();
        Qs[kg*4+0][lr] = qv.x; Qs[kg*4+1][lr] = qv.y;
        Qs[kg*4+2][lr] = qv.z; Qs[kg*4+3][lr] = qv.w;
        Ks[kg*4+0][lr] = kv.x; Ks[kg*4+1][lr] = kv.y;
        Ks[kg*4+2][lr] = kv.z; Ks[kg*4+3][lr] = kv.w;
        __syncthreads();
#pragma unroll
        for (int k = 0; k < 16; k++) {
            float4 a = *(const float4*)&Qs[k][ty * 4];
            float4 c = *(const float4*)&Ks[k][tx * 4];
            float aa[4] = {a.x, a.y, a.z, a.w};
            float cc[4] = {c.x, c.y, c.z, c.w};
#pragma unroll
            for (int i = 0; i < 4; i++)
#pragma unroll
                for (int j = 0; j < 4; j++)
                    acc[i][j] = fmaf(aa[i], cc[j], acc[i][j]);
        }
    }

    float* arow = g_attn + (size_t)bh * SEQ * ATTS;
#pragma unroll
    for (int i = 0; i < 4; i++) {
        int n = n0 + ty * 4 + i;
        if (n >= SEQ) continue;
        const float* qt = g_qtab + (size_t)(b * SEQ + n) * 600 + h * 60;
#pragma unroll
        for (int j = 0; j < 4; j++) {
            int m = m0 + tx * 4 + j;
            if (m >= ATTS) continue;
            float val = 0.f;
            if (m < SEQ) {
                int iv, ih; rpe_idx(n, m, iv, ih);
                val = 0.125f * (acc[i][j] + qt[iv] + qt[30 + ih]);
            }
            arow[(size_t)n * ATTS + m] = val;
        }
    }
}

/* ------------- softmax over m + bin probabilities by (iv, ih) -------------- */
__global__ void __launch_bounds__(256) softmax_kernel()
{
    __shared__ float bins[8][64];
    int wl = threadIdx.x >> 5, lane = threadIdx.x & 31;
    int w = blockIdx.x * 8 + wl;
    if (w >= BHN * SEQ) return;
    int n = w % SEQ;
    float* row = g_attn + (size_t)w * ATTS;

    float e[7]; float mx = -1e30f;
#pragma unroll
    for (int i = 0; i < 7; i++) {
        int m = lane + 32 * i;
        float v = (m < SEQ) ? row[m] : -1e30f;
        e[i] = v; mx = fmaxf(mx, v);
    }
#pragma unroll
    for (int o = 16; o; o >>= 1) mx = fmaxf(mx, __shfl_xor_sync(0xffffffffu, mx, o));
    float s = 0.f;
#pragma unroll
    for (int i = 0; i < 7; i++) {
        int m = lane + 32 * i;
        float ev = (m < SEQ) ? __expf(e[i] - mx) : 0.f;
        e[i] = ev; s += ev;
    }
#pragma unroll
    for (int o = 16; o; o >>= 1) s += __shfl_xor_sync(0xffffffffu, s, o);
    float inv = 1.f / s;

    bins[wl][lane] = 0.f; bins[wl][lane + 32] = 0.f;
    __syncwarp();
#pragma unroll
    for (int i = 0; i < 7; i++) {
        int m = lane + 32 * i;
        if (m < SEQ) {
            float p = e[i] * inv;
            row[m] = p;
            int iv, ih; rpe_idx(n, m, iv, ih);
            atomicAdd(&bins[wl][iv], p);
            atomicAdd(&bins[wl][32 + ih], p);
        }
    }
    __syncwarp();
    float* st = g_stab + (size_t)w * 64;
    for (int t = lane; t < 64; t += 32) {
        float v = (t < 30) ? bins[wl][t] : (t < 60 ? bins[wl][32 + (t - 30)] : 0.f);
        st[t] = v;
    }
}

/* -------- o[b,h,n,:] = P @ V  +  stab @ rcat  (two K-phases, 64x64) -------- */
__global__ void __launch_bounds__(256) attnv_kernel()
{
    __shared__ float As[16][68];
    __shared__ float Bs[16][68];
    int bh = blockIdx.y, b = bh / NH, h = bh - b * NH;
    int n0 = blockIdx.x * 64;
    int tid = threadIdx.x;
    int lr = tid >> 2, kg = tid & 3;
    int kl = tid >> 4, dg = tid & 15;
    int tx = tid & 15, ty = tid >> 4;
    const float* Pb = g_attn + (size_t)bh * SEQ * ATTS;
    const float* Vb = g_qkv  + (size_t)b * SEQ * QKVS + h * HDIM_ + 2 * EMB;
    const float* Sb = g_stab + (size_t)bh * SEQ * 64;
    bool aok = (n0 + lr) < SEQ;

    float acc[4][4];
#pragma unroll
    for (int i = 0; i < 4; i++)
#pragma unroll
        for (int j = 0; j < 4; j++) acc[i][j] = 0.f;

    for (int kt = 0; kt < 13; kt++) {
        float4 av = make_float4(0.f,0.f,0.f,0.f);
        if (aok) av = *(const float4*)(Pb + (size_t)(n0 + lr) * ATTS + kt * 16 + kg * 4);
        int mB = kt * 16 + kl;
        float4 bv = make_float4(0.f,0.f,0.f,0.f);
        if (mB < SEQ) bv = *(const float4*)(Vb + (size_t)mB * QKVS + dg * 4);
        __syncthreads();
        As[kg*4+0][lr] = av.x; As[kg*4+1][lr] = av.y;
        As[kg*4+2][lr] = av.z; As[kg*4+3][lr] = av.w;
        *(float4*)&Bs[kl][dg * 4] = bv;
        __syncthreads();
#pragma unroll
        for (int k = 0; k < 16; k++) {
            float4 a = *(const float4*)&As[k][ty * 4];
            float4 c = *(const float4*)&Bs[k][tx * 4];
            float aa[4] = {a.x, a.y, a.z, a.w};
            float cc[4] = {c.x, c.y, c.z, c.w};
#pragma unroll
            for (int i = 0; i < 4; i++)
#pragma unroll
                for (int j = 0; j < 4; j++)
                    acc[i][j] = fmaf(aa[i], cc[j], acc[i][j]);
        }
    }
    for (int kt = 0; kt < 4; kt++) {
        float4 av = make_float4(0.f,0.f,0.f,0.f);
        if (aok) av = *(const float4*)(Sb + (size_t)(n0 + lr) * 64 + kt * 16 + kg * 4);
        float4 bv = *(const float4*)(g_rcat + (kt * 16 + kl) * 64 + dg * 4);
        __syncthreads();
        As[kg*4+0][lr] = av.x; As[kg*4+1][lr] = av.y;
        As[kg*4+2][lr] = av.z; As[kg*4+3][lr] = av.w;
        *(float4*)&Bs[kl][dg * 4] = bv;
        __syncthreads();
#pragma unroll
        for (int k = 0; k < 16; k++) {
            float4 a = *(const float4*)&As[k][ty * 4];
            float4 c = *(const float4*)&Bs[k][tx * 4];
            float aa[4] = {a.x, a.y, a.z, a.w};
            float cc[4] = {c.x, c.y, c.z, c.w};
#pragma unroll
            for (int i = 0; i < 4; i++)
#pragma unroll
                for (int j = 0; j < 4; j++)
                    acc[i][j] = fmaf(aa[i], cc[j], acc[i][j]);
        }
    }

#pragma unroll
    for (int i = 0; i < 4; i++) {
        int n = n0 + ty * 4 + i;
        if (n >= SEQ) continue;
        float4 vv;
        vv.x = tf32r(acc[i][0]); vv.y = tf32r(acc[i][1]);
        vv.z = tf32r(acc[i][2]); vv.w = tf32r(acc[i][3]);
        *(float4*)(g_o + (size_t)(b * SEQ + n) * EMB + h * HDIM_ + tx * 4) = vv;
    }
}

/* --------------------------------- launch ---------------------------------- */
extern "C" void kernel_launch(void* const* d_in, const int* in_sizes, int n_in,
                              void* d_out, int out_size)
{
    const float* x     = (const float*)d_in[0];
    const float* ln1_g = (const float*)d_in[1];
    const float* ln1_b = (const float*)d_in[2];
    const float* Wq    = (const float*)d_in[3];
    const float* Wk    = (const float*)d_in[4];
    const float* Wv    = (const float*)d_in[5];
    const float* Wp    = (const float*)d_in[6];
    const float* bp    = (const float*)d_in[7];
    const float* rpk_v = (const float*)d_in[8];
    const float* rpk_h = (const float*)d_in[9];
    const float* rpv_v = (const float*)d_in[10];
    const float* rpv_h = (const float*)d_in[11];
    const float* ln2_g = (const float*)d_in[12];
    const float* ln2_b = (const float*)d_in[13];
    const float* W1    = (const float*)d_in[14];
    const float* b1    = (const float*)d_in[15];
    const float* W2    = (const float*)d_in[16];
    const float* b2    = (const float*)d_in[17];

    float *ph, *pqkv, *po, *px1, *pffn;
    float *pwqkv, *pwp, *pw1, *pw2;
    cudaGetSymbolAddress((void**)&ph,    g_h);
    cudaGetSymbolAddress((void**)&pqkv,  g_qkv);
    cudaGetSymbolAddress((void**)&po,    g_o);
    cudaGetSymbolAddress((void**)&px1,   g_x1);
    cudaGetSymbolAddress((void**)&pffn,  g_ffn);
    cudaGetSymbolAddress((void**)&pwqkv, g_wqkv);
    cudaGetSymbolAddress((void**)&pwp,   g_wp);
    cudaGetSymbolAddress((void**)&pw1,   g_w1);
    cudaGetSymbolAddress((void**)&pw2,   g_w2);

    const int MB = (MROWS + 127) / 128;   /* 99 */
    const int WEE = EMB * EMB, WFE = FF * EMB;

    /* weight pre-rounding (tf32) */
    round_qkv<<<(3 * WEE + 255) / 256, 256>>>(Wq, Wk, Wv);
    round_copy<<<(WEE + 255) / 256, 256>>>(Wp, pwp, WEE);
    round_copy<<<(WFE + 255) / 256, 256>>>(W1, pw1, WFE);
    round_copy<<<(WFE + 255) / 256, 256>>>(W2, pw2, WFE);

    /* LN1 (tf32-rounded output) */
    ln_kernel<<<MROWS / 8, 256>>>(x, ln1_g, ln1_b, ph);
    /* fused QKV projection */
    gemm_tc<false,false><<<dim3(QKVS / 128, MB), 256>>>(ph, pwqkv, nullptr, nullptr, pqkv, EMB, QKVS, MROWS);
    /* RPE precomputes */
    build_rcat<<<16, 256>>>(rpv_v, rpv_h);
    qtab_kernel<<<MROWS, 256>>>(rpk_v, rpk_h);
    /* attention (SIMT — best known config) */
    scores_kernel<<<dim3(4, 4, BHN), 256>>>();
    softmax_kernel<<<(BHN * SEQ + 7) / 8, 256>>>();
    attnv_kernel<<<dim3(4, BHN), 256>>>();
    /* output projection + residual */
    gemm_tc<false,false><<<dim3(EMB / 128, MB), 256>>>(po, pwp, bp, x, px1, EMB, EMB, MROWS);
    /* FFN block */
    ln_kernel<<<MROWS / 8, 256>>>(px1, ln2_g, ln2_b, ph);
    gemm_tc<true ,true ><<<dim3(FF / 128, MB), 256>>>(ph, pw1, b1, nullptr, pffn, EMB, FF, MROWS);
    gemm_tc<false,false><<<dim3(EMB / 128, MB), 256>>>(pffn, pw2, b2, px1, (float*)d_out, FF, EMB, MROWS);
}